// round 13
// baseline (speedup 1.0000x reference)
#include <cuda_runtime.h>
#include <cuda_bf16.h>
#include <math.h>
#include <stdint.h>

#define N_    512
#define H_    8
#define C_    128
#define PQ_   8
#define PV_   8
#define KF_   160
#define OC_   256
#define SEG_  312
#define FEAT_ 2496
#define PROJ_ 3584
#define NN_   ((size_t)N_*N_)

// ---------------- scratch ----------------
static __device__ float g_Wcat[384*PROJ_];
static __device__ float g_bcat[PROJ_];
static __device__ float g_proj[(size_t)N_*PROJ_];
static __device__ float g_Qf[(size_t)H_*N_*KF_];
static __device__ float g_Kf[(size_t)H_*N_*KF_];
static __device__ float g_rowc[H_*N_];
static __device__ float g_colc[H_*N_];
static __device__ float g_qn[N_*4];
static __device__ float g_tr[N_*3];
static __device__ float g_qntr[N_*8];
static __device__ float g_hw[H_];
static __device__ float g_pairb[(size_t)H_*NN_];   // [h][i][j]
static __device__ float g_zdz[(size_t)NN_*32];
static __device__ float g_A[(size_t)H_*N_*N_];
static __device__ float g_Vcat[(size_t)H_*N_*OC_];
static __device__ float g_Ocat[(size_t)H_*N_*OC_];
static __device__ float g_Orel[(size_t)H_*N_*8];
static __device__ float g_feats[(size_t)N_*FEAT_];
static __device__ __nv_bfloat16 g_Whz[40*128];
static __device__ __nv_bfloat16 g_Wlz[40*128];

// ---------------- mma helpers ----------------
__device__ __forceinline__ void mma_bf16(float* d, const uint32_t* a, const uint32_t* b) {
    asm volatile(
        "mma.sync.aligned.m16n8k16.row.col.f32.bf16.bf16.f32 "
        "{%0,%1,%2,%3}, {%4,%5,%6,%7}, {%8,%9}, {%0,%1,%2,%3};"
        : "+f"(d[0]), "+f"(d[1]), "+f"(d[2]), "+f"(d[3])
        : "r"(a[0]), "r"(a[1]), "r"(a[2]), "r"(a[3]), "r"(b[0]), "r"(b[1]));
}
__device__ __forceinline__ uint32_t packbf2(float x, float y) {
    __nv_bfloat16 hx = __float2bfloat16(x), hy = __float2bfloat16(y);
    return (uint32_t)__bfloat16_as_ushort(hx) | ((uint32_t)__bfloat16_as_ushort(hy) << 16);
}
__device__ __forceinline__ uint32_t packlo2(float x, float y) {
    float rx = x - __bfloat162float(__float2bfloat16(x));
    float ry = y - __bfloat162float(__float2bfloat16(y));
    return packbf2(rx, ry);
}
__device__ __forceinline__ void splitf(float v, uint16_t& h, uint16_t& l) {
    __nv_bfloat16 hb = __float2bfloat16(v);
    h = __bfloat16_as_ushort(hb);
    l = __bfloat16_as_ushort(__float2bfloat16(v - __bfloat162float(hb)));
}
__device__ __forceinline__ void loadA_direct(const float* Abase, int lda, int kb,
                                             uint32_t* ah, uint32_t* al) {
    float2 v0 = *(const float2*)(Abase + kb);
    float2 v1 = *(const float2*)(Abase + (size_t)8*lda + kb);
    float2 v2 = *(const float2*)(Abase + kb + 8);
    float2 v3 = *(const float2*)(Abase + (size_t)8*lda + kb + 8);
    ah[0] = packbf2(v0.x, v0.y);  al[0] = packlo2(v0.x, v0.y);
    ah[1] = packbf2(v1.x, v1.y);  al[1] = packlo2(v1.x, v1.y);
    ah[2] = packbf2(v2.x, v2.y);  al[2] = packlo2(v2.x, v2.y);
    ah[3] = packbf2(v3.x, v3.y);  al[3] = packlo2(v3.x, v3.y);
}

// shared-tile GEMM geometry (R9-proven)
#define AST 40
#define BST 40
#define AH_OFF 0
#define AL_OFF 10240
#define BH_OFF 20480
#define BL_OFF 25600
#define GSM    30720

__device__ __forceinline__ void stageA128(char* sm, const float* A, int lda, int k0, int tid) {
    #pragma unroll
    for (int i = tid*4; i < 4096; i += 1024) {
        int r = i >> 5, k = i & 31;
        float4 v = *(const float4*)(A + (size_t)r*lda + k0 + k);
        char* ph = sm + AH_OFF + (r*AST + k)*2;
        *(uint32_t*)(ph)   = packbf2(v.x, v.y);
        *(uint32_t*)(ph+4) = packbf2(v.z, v.w);
        char* pl = sm + AL_OFF + (r*AST + k)*2;
        *(uint32_t*)(pl)   = packlo2(v.x, v.y);
        *(uint32_t*)(pl+4) = packlo2(v.z, v.w);
    }
}
__device__ __forceinline__ void stageB64_nt(char* sm, const float* B, int ldb, int k0, int tid) {
    #pragma unroll
    for (int i = tid*4; i < 2048; i += 1024) {
        int n = i >> 5, k = i & 31;
        float4 v = *(const float4*)(B + (size_t)n*ldb + k0 + k);
        char* ph = sm + BH_OFF + (n*BST + k)*2;
        *(uint32_t*)(ph)   = packbf2(v.x, v.y);
        *(uint32_t*)(ph+4) = packbf2(v.z, v.w);
        char* pl = sm + BL_OFF + (n*BST + k)*2;
        *(uint32_t*)(pl)   = packlo2(v.x, v.y);
        *(uint32_t*)(pl+4) = packlo2(v.z, v.w);
    }
}
__device__ __forceinline__ void stageB64_nn(char* sm, const float* B, int ldb, int k0, int tid) {
    #pragma unroll
    for (int i = tid*4; i < 2048; i += 1024) {
        int k = i >> 6, n = i & 63;
        float4 v = *(const float4*)(B + (size_t)(k0+k)*ldb + n);
        float vv[4] = {v.x, v.y, v.z, v.w};
        #pragma unroll
        for (int j = 0; j < 4; j++) {
            uint16_t h, l; splitf(vv[j], h, l);
            *(uint16_t*)(sm + BH_OFF + ((n+j)*BST + k)*2) = h;
            *(uint16_t*)(sm + BL_OFF + ((n+j)*BST + k)*2) = l;
        }
    }
}
__device__ __forceinline__ void tile_mma(const char* sm, int warp, int lane, float (*acc)[4][4]) {
    int gid = lane >> 2, tid4 = lane & 3;
    int m0 = (warp >> 1)*32, n0 = (warp & 1)*32;
    #pragma unroll
    for (int ks = 0; ks < 2; ks++) {
        int kb = ks*16 + tid4*2;
        uint32_t ah[2][4], al[2][4];
        #pragma unroll
        for (int t = 0; t < 2; t++) {
            const char* ba = sm + AH_OFF + ((m0 + t*16 + gid)*AST + kb)*2;
            ah[t][0] = *(const uint32_t*)(ba);
            ah[t][1] = *(const uint32_t*)(ba + 8*AST*2);
            ah[t][2] = *(const uint32_t*)(ba + 16);
            ah[t][3] = *(const uint32_t*)(ba + 8*AST*2 + 16);
            const char* bal = ba + (AL_OFF - AH_OFF);
            al[t][0] = *(const uint32_t*)(bal);
            al[t][1] = *(const uint32_t*)(bal + 8*AST*2);
            al[t][2] = *(const uint32_t*)(bal + 16);
            al[t][3] = *(const uint32_t*)(bal + 8*AST*2 + 16);
        }
        #pragma unroll
        for (int u = 0; u < 4; u++) {
            const char* bb = sm + BH_OFF + ((n0 + u*8 + gid)*BST + kb)*2;
            uint32_t bh[2] = { *(const uint32_t*)bb, *(const uint32_t*)(bb+16) };
            const char* bbl = bb + (BL_OFF - BH_OFF);
            uint32_t bl2[2] = { *(const uint32_t*)bbl, *(const uint32_t*)(bbl+16) };
            #pragma unroll
            for (int t = 0; t < 2; t++) {
                mma_bf16(acc[t][u], ah[t], bh);
                mma_bf16(acc[t][u], al[t], bh);
                mma_bf16(acc[t][u], ah[t], bl2);
            }
        }
    }
}

// ---------------- misc helpers ----------------
__device__ __forceinline__ void qrot(const float* q, const float* v, float* o) {
    float w=q[0], x=q[1], y=q[2], z=q[3];
    float uvx = y*v[2]-z*v[1];
    float uvy = z*v[0]-x*v[2];
    float uvz = x*v[1]-y*v[0];
    float uuvx = y*uvz-z*uvy;
    float uuvy = z*uvx-x*uvz;
    float uuvz = x*uvy-y*uvx;
    o[0]=v[0]+2.f*(w*uvx+uuvx);
    o[1]=v[1]+2.f*(w*uvy+uuvy);
    o[2]=v[2]+2.f*(w*uvz+uuvz);
}

// ---------------- frames + head weights ----------------
__global__ void frames_kernel(const float* __restrict__ T, const float* __restrict__ head_weights) {
    int n = blockIdx.x*blockDim.x + threadIdx.x;
    if (n < N_) {
        const float* t = T + n*16;
        float q0=t[0], q1=t[1], q2=t[2], q3=t[3];
        float inv = rsqrtf(q0*q0+q1*q1+q2*q2+q3*q3 + 1e-8f);
        g_qn[n*4+0]=q0*inv; g_qn[n*4+1]=q1*inv; g_qn[n*4+2]=q2*inv; g_qn[n*4+3]=q3*inv;
        g_tr[n*3+0]=t[4]; g_tr[n*3+1]=t[5]; g_tr[n*3+2]=t[6];
        g_qntr[n*8+0]=q0*inv; g_qntr[n*8+1]=q1*inv; g_qntr[n*8+2]=q2*inv; g_qntr[n*8+3]=q3*inv;
        g_qntr[n*8+4]=t[4]; g_qntr[n*8+5]=t[5]; g_qntr[n*8+6]=t[6]; g_qntr[n*8+7]=0.f;
    }
    if (n < H_) {
        float x = head_weights[n];
        float sp = (x > 20.f) ? x : log1pf(expf(x));
        g_hw[n] = sp * rsqrtf(108.0f);
    }
}

// ---------------- W prep (zfuse B tiles) ----------------
__global__ void wprep_kernel(const float* __restrict__ W_b, const float* __restrict__ W_dz) {
    int idx = blockIdx.x*256 + threadIdx.x;
    if (idx >= 40*128) return;
    int n = idx >> 7, k = idx & 127;
    float v = (n < 8) ? W_b[k*8 + n] : W_dz[k*32 + (n-8)];
    __nv_bfloat16 h = __float2bfloat16(v);
    g_Whz[idx] = h;
    g_Wlz[idx] = __float2bfloat16(v - __bfloat162float(h));
}

// ---------------- weight packing ----------------
__global__ void pack_kernel(const float* __restrict__ W_q, const float* __restrict__ W_kv,
                            const float* __restrict__ W_qp, const float* __restrict__ W_kp,
                            const float* __restrict__ W_vg,
                            const float* __restrict__ b_q, const float* __restrict__ b_kv,
                            const float* __restrict__ b_qp, const float* __restrict__ b_kp,
                            const float* __restrict__ b_vg) {
    int idx = blockIdx.x*256 + threadIdx.x;
    if (idx >= 384*PROJ_) return;
    int k = idx / PROJ_, c = idx % PROJ_;
    float v;
    if      (c < 1024) v = W_q [k*1024 + c];
    else if (c < 3072) v = W_kv[k*2048 + (c-1024)];
    else if (c < 3264) v = W_qp[k*192  + (c-3072)];
    else if (c < 3456) v = W_kp[k*192  + (c-3264)];
    else               v = W_vg[k*128  + (c-3456)];
    g_Wcat[idx] = v;
    if (k == 0) {
        float b;
        if      (c < 1024) b = b_q [c];
        else if (c < 3072) b = b_kv[c-1024];
        else if (c < 3264) b = b_qp[c-3072];
        else if (c < 3456) b = b_kp[c-3264];
        else               b = b_vg[c-3456];
        g_bcat[c] = b;
    }
}

// ---------------- zfuse body ----------------
#define ZWST 272
__device__ __forceinline__ void zfuse_body(char* sm, int bidx,
                                           const float* __restrict__ z,
                                           const float* __restrict__ b_dz) {
    int tid = threadIdx.x;
    int warp = tid >> 5, lane = tid & 31;
    int gid = lane >> 2, tid4 = lane & 3;
    {
        const uint32_t* wh32 = (const uint32_t*)g_Whz;
        const uint32_t* wl32 = (const uint32_t*)g_Wlz;
        for (int i = tid; i < 40*64; i += 256) {
            int n = i >> 6, kw = i & 63;
            *(uint32_t*)(sm + n*ZWST + kw*4)           = wh32[i];
            *(uint32_t*)(sm + 40*ZWST + n*ZWST + kw*4) = wl32[i];
        }
    }
    __syncthreads();

    size_t p0 = (size_t)bidx * 256;
    const float* zb = z + (p0 + warp*32 + gid)*128;

    float acc[2][5][4] = {};
    #pragma unroll
    for (int ks = 0; ks < 8; ks++) {
        int kb = ks*16 + tid4*2;
        uint32_t ah[2][4], al[2][4];
        #pragma unroll
        for (int t = 0; t < 2; t++)
            loadA_direct(zb + (size_t)t*16*128, 128, kb, ah[t], al[t]);
        #pragma unroll
        for (int nt = 0; nt < 5; nt++) {
            int ob = (nt*8 + gid)*ZWST + kb*2;
            uint32_t bh[2], bl[2];
            bh[0] = *(const uint32_t*)(sm + ob);
            bh[1] = *(const uint32_t*)(sm + ob + 16);
            bl[0] = *(const uint32_t*)(sm + 40*ZWST + ob);
            bl[1] = *(const uint32_t*)(sm + 40*ZWST + ob + 16);
            #pragma unroll
            for (int t = 0; t < 2; t++) {
                mma_bf16(acc[t][nt], ah[t], bh);
                mma_bf16(acc[t][nt], al[t], bh);
                mma_bf16(acc[t][nt], ah[t], bl);
            }
        }
    }

    #pragma unroll
    for (int t = 0; t < 2; t++) {
        size_t r0 = p0 + warp*32 + t*16 + gid;
        size_t r1 = r0 + 8;
        int c0 = tid4*2;
        g_pairb[(size_t)(c0  )*NN_ + r0] = acc[t][0][0];
        g_pairb[(size_t)(c0+1)*NN_ + r0] = acc[t][0][1];
        g_pairb[(size_t)(c0  )*NN_ + r1] = acc[t][0][2];
        g_pairb[(size_t)(c0+1)*NN_ + r1] = acc[t][0][3];
        #pragma unroll
        for (int nt = 1; nt < 5; nt++) {
            int zc = nt*8 + tid4*2 - 8;
            float bz0 = b_dz[zc], bz1 = b_dz[zc+1];
            *(float2*)(g_zdz + r0*32 + zc) = make_float2(acc[t][nt][0] + bz0, acc[t][nt][1] + bz1);
            *(float2*)(g_zdz + r1*32 + zc) = make_float2(acc[t][nt][2] + bz0, acc[t][nt][3] + bz1);
        }
    }
}

// ---------------- proj body ----------------
__device__ __forceinline__ void proj_body(char* sm, int pidx, const float* __restrict__ s) {
    int tid = threadIdx.x, warp = tid >> 5, lane = tid & 31;
    int nBase = (pidx % 56)*64, rowBase = (pidx / 56)*128;
    const float* A = s + (size_t)rowBase*384;
    const float* B = g_Wcat + nBase;
    float acc[2][4][4] = {};
    for (int k0 = 0; k0 < 384; k0 += 32) {
        __syncthreads();
        stageA128(sm, A, 384, k0, tid);
        stageB64_nn(sm, B, PROJ_, k0, tid);
        __syncthreads();
        tile_mma(sm, warp, lane, acc);
    }
    int gid = lane >> 2, tid4 = lane & 3;
    int m0 = (warp >> 1)*32, n0w = (warp & 1)*32;
    #pragma unroll
    for (int t = 0; t < 2; t++) {
        int r0 = rowBase + m0 + t*16 + gid;
        #pragma unroll
        for (int u = 0; u < 4; u++) {
            int c = nBase + n0w + u*8 + tid4*2;
            float b0 = g_bcat[c], b1 = g_bcat[c+1];
            *(float2*)(g_proj + (size_t)r0*PROJ_ + c)     = make_float2(acc[t][u][0]+b0, acc[t][u][1]+b1);
            *(float2*)(g_proj + (size_t)(r0+8)*PROJ_ + c) = make_float2(acc[t][u][2]+b0, acc[t][u][3]+b1);
        }
    }
}

// ---------------- merged zfuse + proj ----------------
__global__ void __launch_bounds__(256) zfuse_proj_kernel(const float* __restrict__ z,
                                                         const float* __restrict__ b_dz,
                                                         const float* __restrict__ s) {
    __shared__ __align__(16) char sm[GSM];
    if (blockIdx.x < 1024) zfuse_body(sm, blockIdx.x, z, b_dz);
    else                   proj_body(sm, blockIdx.x - 1024, s);
}

// ---------------- logits (R9 staged) ----------------
__global__ void __launch_bounds__(256) logits_mma(const float* __restrict__ b_b,
                                                  const float* __restrict__ sw,
                                                  const float* __restrict__ mask) {
    __shared__ __align__(16) char sm[GSM];
    int tid = threadIdx.x, warp = tid >> 5, lane = tid & 31;
    int h = blockIdx.z;
    int rowBase = blockIdx.y*128, nBase = blockIdx.x*64;
    const float* A = g_Qf + ((size_t)h*N_ + rowBase)*KF_;
    const float* B = g_Kf + ((size_t)h*N_ + nBase)*KF_;
    float acc[2][4][4] = {};
    for (int k0 = 0; k0 < KF_; k0 += 32) {
        __syncthreads();
        stageA128(sm, A, KF_, k0, tid);
        stageB64_nt(sm, B, KF_, k0, tid);
        __syncthreads();
        tile_mma(sm, warp, lane, acc);
    }
    const float s2 = 0.57735026918962576f;
    float swh = sw[h], bbh = b_b[h];
    const float* pbh = g_pairb + (size_t)h*NN_;
    int gid = lane >> 2, tid4 = lane & 3;
    int m0 = (warp >> 1)*32, n0w = (warp & 1)*32;
    #pragma unroll
    for (int t = 0; t < 2; t++) {
        int gi0 = rowBase + m0 + t*16 + gid;
        int gi1 = gi0 + 8;
        float rc0 = g_rowc[h*N_+gi0], rc1 = g_rowc[h*N_+gi1];
        float mi0 = mask[gi0], mi1 = mask[gi1];
        #pragma unroll
        for (int u = 0; u < 4; u++) {
            int gc = nBase + n0w + u*8 + tid4*2;
            float2 pb0 = *(const float2*)(pbh + (size_t)gi0*N_ + gc);
            float2 pb1 = *(const float2*)(pbh + (size_t)gi1*N_ + gc);
            #pragma unroll
            for (int j = 0; j < 2; j++) {
                int c = gc + j;
                float cc = g_colc[h*N_+c], mj = mask[c];
                float p0 = j ? pb0.y : pb0.x;
                float p1 = j ? pb1.y : pb1.x;
                float v0 = acc[t][u][j]   + rc0 + cc + s2*(p0+bbh) + 100000.0f*(mi0*mj-1.0f);
                float v1 = acc[t][u][2+j] + rc1 + cc + s2*(p1+bbh) + 100000.0f*(mi1*mj-1.0f);
                g_A[((size_t)h*N_+gi0)*N_ + c] = v0*swh;
                g_A[((size_t)h*N_+gi1)*N_ + c] = v1*swh;
            }
        }
    }
}

// ---------------- av body (R9 staged) ----------------
__device__ __forceinline__ void av_body(char* sm, int aidx) {
    int tid = threadIdx.x, warp = tid >> 5, lane = tid & 31;
    int h = aidx >> 4;
    int nBase = (aidx & 3)*64, rowBase = ((aidx >> 2) & 3)*128;
    const float* A = g_A + ((size_t)h*N_ + rowBase)*N_;
    const float* B = g_Vcat + (size_t)h*N_*OC_ + nBase;
    float acc[2][4][4] = {};
    for (int k0 = 0; k0 < N_; k0 += 32) {
        __syncthreads();
        stageA128(sm, A, N_, k0, tid);
        stageB64_nn(sm, B, OC_, k0, tid);
        __syncthreads();
        tile_mma(sm, warp, lane, acc);
    }
    int gid = lane >> 2, tid4 = lane & 3;
    int m0 = (warp >> 1)*32, n0w = (warp & 1)*32;
    #pragma unroll
    for (int t = 0; t < 2; t++) {
        int r0 = rowBase + m0 + t*16 + gid;
        #pragma unroll
        for (int u = 0; u < 4; u++) {
            int c = nBase + n0w + u*8 + tid4*2;
            *(float2*)(g_Ocat + ((size_t)h*N_ + r0)*OC_ + c)   = make_float2(acc[t][u][0], acc[t][u][1]);
            *(float2*)(g_Ocat + ((size_t)h*N_ + r0+8)*OC_ + c) = make_float2(acc[t][u][2], acc[t][u][3]);
        }
    }
}

// ---------------- opair body (R9 staged version) ----------------
__device__ __forceinline__ void opair_body(char* smraw, int i) {
    float* Zs  = (float*)smraw;             // 64*33 floats
    float* Asm = ((float*)smraw) + 64*33;   // 8*64 floats
    int tid = threadIdx.x;
    int hh = tid>>5, cc = tid&31;
    float acc = 0.f;
    for (int jt=0; jt<N_; jt+=64) {
        __syncthreads();
        for (int t=tid; t<2048; t+=256) {
            int jj=t>>5, c=t&31;
            Zs[jj*33+c] = g_zdz[((size_t)i*N_ + jt+jj)*32 + c];
        }
        for (int t=tid; t<512; t+=256) {
            int h=t>>6, jj=t&63;
            Asm[h*64+jj] = g_A[((size_t)h*N_+i)*N_ + jt+jj];
        }
        __syncthreads();
        #pragma unroll
        for (int jj=0; jj<64; jj++) acc += Asm[hh*64+jj]*Zs[jj*33+cc];
    }
    g_feats[(size_t)i*FEAT_ + hh*SEG_ + cc] = acc;
}

// ---------------- merged av + opair ----------------
__global__ void __launch_bounds__(256) av_opair_kernel() {
    __shared__ __align__(16) char sm[GSM];
    if (blockIdx.x < 128) av_body(sm, blockIdx.x);
    else                  opair_body(sm, blockIdx.x - 128);
}

// ---------------- wout body (R9 staged; 144 blocks: 6 n x 4 row x 6 ksplit) ----------------
__device__ __forceinline__ void wout_body(char* sm, int widx,
                                          const float* __restrict__ W_out,
                                          float* __restrict__ out) {
    int tid = threadIdx.x, warp = tid >> 5, lane = tid & 31;
    int nBase = (widx % 6)*64;
    int rowBase = ((widx / 6) % 4)*128;
    int kstart = (widx / 24)*416;
    const float* A = g_feats + (size_t)rowBase*FEAT_;
    const float* B = W_out + nBase;
    float acc[2][4][4] = {};
    for (int k0 = kstart; k0 < kstart + 416; k0 += 32) {
        __syncthreads();
        stageA128(sm, A, FEAT_, k0, tid);
        stageB64_nn(sm, B, 384, k0, tid);
        __syncthreads();
        tile_mma(sm, warp, lane, acc);
    }
    int gid = lane >> 2, tid4 = lane & 3;
    int m0 = (warp >> 1)*32, n0w = (warp & 1)*32;
    #pragma unroll
    for (int t = 0; t < 2; t++) {
        int r0 = rowBase + m0 + t*16 + gid;
        #pragma unroll
        for (int u = 0; u < 4; u++) {
            int c = nBase + n0w + u*8 + tid4*2;
            atomicAdd(&out[(size_t)r0*384 + c],       acc[t][u][0]);
            atomicAdd(&out[(size_t)r0*384 + c + 1],   acc[t][u][1]);
            atomicAdd(&out[(size_t)(r0+8)*384 + c],   acc[t][u][2]);
            atomicAdd(&out[(size_t)(r0+8)*384 + c+1], acc[t][u][3]);
        }
    }
}

// ---------------- gout body ----------------
__device__ __forceinline__ void gout_body(int gidx, const float* __restrict__ W_geo,
                                          float* __restrict__ gout) {
    int tid = threadIdx.x;
    int n = gidx*2 + (tid >> 7);
    int t128 = tid & 127;
    int o = t128 >> 4, c = t128 & 15;
    float acc = 0.f;
    #pragma unroll
    for (int i2 = 0; i2 < 64; i2++) {
        acc += W_geo[o*64+i2] * g_feats[(size_t)n*FEAT_ + (i2>>3)*SEG_ + 168 + (i2&7)*16 + c];
    }
    gout[(size_t)n*128 + o*16 + c] = acc;
}

// ---------------- merged wout + gout ----------------
__global__ void __launch_bounds__(256) wout_gout_kernel(const float* __restrict__ W_out,
                                                        const float* __restrict__ W_geo,
                                                        float* __restrict__ out) {
    __shared__ __align__(16) char sm[GSM];
    if (blockIdx.x < 144) wout_body(sm, blockIdx.x, W_out, out);
    else                  gout_body(blockIdx.x - 144, W_geo, out + 512*384);
}

// ---------------- point transforms + Qf/Kf packing ----------------
__global__ void pts_pack_kernel() {
    int n = blockIdx.x, tid = threadIdx.x;   // 128 threads
    __shared__ float sq[64*3], sk[64*3];
    __shared__ float qsq[H_], ksq[H_];
    __shared__ float qn[4], tr[3];
    if (tid<4) qn[tid]=g_qn[n*4+tid];
    if (tid>=4 && tid<7) tr[tid-4]=g_tr[n*3+tid-4];
    if (tid<H_) { qsq[tid]=0.f; ksq[tid]=0.f; }
    __syncthreads();
    if (tid < 64) {
        float p[3], o[3];
        #pragma unroll
        for (int d=0; d<3; d++) p[d]=g_proj[(size_t)n*PROJ_ + 3072 + d*64 + tid];
        qrot(qn, p, o);
        float ss=0.f;
        #pragma unroll
        for (int d=0; d<3; d++) { o[d]+=tr[d]; sq[tid*3+d]=o[d]; ss+=o[d]*o[d]; }
        atomicAdd(&qsq[tid>>3], ss);
        #pragma unroll
        for (int d=0; d<3; d++) p[d]=g_proj[(size_t)n*PROJ_ + 3264 + d*64 + tid];
        qrot(qn, p, o);
        ss=0.f;
        #pragma unroll
        for (int d=0; d<3; d++) { o[d]+=tr[d]; sk[tid*3+d]=o[d]; ss+=o[d]*o[d]; }
        atomicAdd(&ksq[tid>>3], ss);
    }
    __syncthreads();
    float s1 = rsqrtf(384.f);
    for (int t=tid; t<H_*KF_; t+=128) {
        int h=t/KF_, c=t%KF_;
        float qv, kv;
        if (c < C_) {
            qv = g_proj[(size_t)n*PROJ_ + h*C_ + c] * s1;
            kv = g_proj[(size_t)n*PROJ_ + 1024 + h*256 + c];
        } else if (c < 152) {
            int m=c-128, pp=m/3, d=m%3;
            int idx=(h*PQ_+pp)*3+d;
            qv = sq[idx]*g_hw[h];
            kv = sk[idx];
        } else { qv=0.f; kv=0.f; }
        g_Qf[((size_t)h*N_+n)*KF_ + c] = qv;
        g_Kf[((size_t)h*N_+n)*KF_ + c] = kv;
    }
    if (tid < H_) {
        g_rowc[tid*N_+n] = -0.5f*g_hw[tid]*qsq[tid];
        g_colc[tid*N_+n] = -0.5f*g_hw[tid]*ksq[tid];
    }
}

// ---------------- v_g mix + mv_transform + Vcat assembly ----------------
__global__ void vg_kernel(const float* __restrict__ gin, const float* __restrict__ W_mg) {
    int n = blockIdx.x, tid = threadIdx.x;   // 128 threads
    __shared__ float cat16[16*16];
    __shared__ float mix[64*16];
    __shared__ float qn[4], tr[3];
    if (tid<4) qn[tid]=g_qn[n*4+tid];
    if (tid>=4 && tid<7) tr[tid-4]=g_tr[n*3+tid-4];
    {
        int p=tid>>4, c=tid&15;
        cat16[p*16+c]     = g_proj[(size_t)n*PROJ_ + 3456 + p*16 + c];
        cat16[(p+8)*16+c] = gin  [(size_t)n*128 + p*16 + c];
    }
    __syncthreads();
    for (int t=tid; t<1024; t+=128) {
        int o=t>>4, c=t&15;
        float acc=0.f;
        #pragma unroll
        for (int i=0;i<16;i++) acc += W_mg[o*16+i]*cat16[i*16+c];
        mix[t]=acc;
    }
    __syncthreads();
    if (tid < 64) {
        int o=tid, h=o>>3, p=o&7;
        float mv[16];
        #pragma unroll
        for (int c=0;c<16;c++) mv[c]=mix[o*16+c];
        float out[16];
        out[0]=mv[0];
        qrot(qn, mv+1, out+1);
        qrot(qn, mv+4, out+4);
        float pv[3]; qrot(qn, mv+7, pv);
        float w=mv[10];
        out[7]=pv[0]+w*tr[0]; out[8]=pv[1]+w*tr[1]; out[9]=pv[2]+w*tr[2];
        #pragma unroll
        for (int c=10;c<16;c++) out[c]=mv[c];
        float* dst = g_Vcat + ((size_t)h*N_+n)*OC_ + 128 + p*16;
        #pragma unroll
        for (int c=0;c<16;c++) dst[c]=out[c];
    }
    for (int t=tid; t<H_*C_; t+=128) {
        int h=t>>7, c=t&127;
        g_Vcat[((size_t)h*N_+n)*OC_ + c] = g_proj[(size_t)n*PROJ_ + 1024 + h*256 + 128 + c];
    }
}

// ---------------- row softmax + fused o_rel accumulation ----------------
__global__ void __launch_bounds__(256) softmax_kernel() {
    __shared__ float qt[512*9];
    int tid = threadIdx.x;
    int warp = tid >> 5, lane = tid & 31;
    for (int t = tid; t < 512; t += 256) {
        #pragma unroll
        for (int c=0;c<8;c++) qt[t*9+c] = g_qntr[t*8+c];
    }
    __syncthreads();
    int row = blockIdx.x*8 + warp;
    float* a = g_A + (size_t)row*N_;
    float v[16];
    #pragma unroll
    for (int t=0;t<16;t++) v[t] = a[lane + 32*t];
    float m = v[0];
    #pragma unroll
    for (int t=1;t<16;t++) m = fmaxf(m, v[t]);
    #pragma unroll
    for (int off=16; off>0; off>>=1) m = fmaxf(m, __shfl_xor_sync(0xffffffff, m, off));
    float s = 0.f;
    #pragma unroll
    for (int t=0;t<16;t++) { v[t] = expf(v[t]-m); s += v[t]; }
    #pragma unroll
    for (int off=16; off>0; off>>=1) s += __shfl_xor_sync(0xffffffff, s, off);
    float inv = 1.f/s;
    float orel[8] = {};
    #pragma unroll
    for (int t=0;t<16;t++) {
        float p = v[t]*inv;
        a[lane + 32*t] = p;
        const float* q = qt + (lane + 32*t)*9;
        #pragma unroll
        for (int c=0;c<8;c++) orel[c] += p*q[c];
    }
    #pragma unroll
    for (int c=0;c<8;c++) {
        #pragma unroll
        for (int off=16; off>0; off>>=1)
            orel[c] += __shfl_xor_sync(0xffffffff, orel[c], off);
    }
    if (lane == 0) {
        #pragma unroll
        for (int c=0;c<8;c++) g_Orel[(size_t)row*8+c] = orel[c];
    }
}

// ---------------- finalize ----------------
__global__ void finalize_kernel() {
    int n = blockIdx.x, tid = threadIdx.x;  // 128
    __shared__ float qn[4], tr[3];
    if (tid<4) qn[tid]=g_qn[n*4+tid];
    if (tid>=4 && tid<7) tr[tid-4]=g_tr[n*3+tid-4];
    __syncthreads();
    for (int t=tid; t<H_*C_; t+=128) {
        int h=t>>7, c=t&127;
        g_feats[(size_t)n*FEAT_ + h*SEG_ + 32 + c] = g_Ocat[((size_t)h*N_+n)*OC_ + c];
    }
    if (tid < 64) {
        int h=tid>>3, p=tid&7;
        const float* oc = g_Ocat + ((size_t)h*N_+n)*OC_ + 128 + p*16;
        float mv[16];
        #pragma unroll
        for (int c=0;c<16;c++) mv[c]=oc[c];
        float qc[4] = {qn[0], -qn[1], -qn[2], -qn[3]};
        float out[16];
        out[0]=mv[0];
        qrot(qc, mv+1, out+1);
        qrot(qc, mv+4, out+4);
        float w=mv[10];
        float tmp[3] = {mv[7]-w*tr[0], mv[8]-w*tr[1], mv[9]-w*tr[2]};
        qrot(qc, tmp, out+7);
        #pragma unroll
        for (int c=10;c<16;c++) out[c]=mv[c];
        float s1v=1e-8f, s2v=1e-8f;
        #pragma unroll
        for (int c=0;c<10;c++) s1v += out[c]*out[c];
        #pragma unroll
        for (int c=10;c<16;c++) s2v += out[c]*out[c];
        float* f = g_feats + (size_t)n*FEAT_ + h*SEG_;
        #pragma unroll
        for (int c=0;c<16;c++) f[168+p*16+c]=out[c];
        f[296+p*2+0]=sqrtf(s1v);
        f[296+p*2+1]=sqrtf(s2v);
    }
    if (tid < H_) {
        int h=tid;
        const float* oc = g_Orel + ((size_t)h*N_+n)*8;
        float aq0=oc[0], aq1=oc[1], aq2=oc[2], aq3=oc[3];
        float qc[4] = {qn[0], -qn[1], -qn[2], -qn[3]};
        float qr0 = qc[0]*aq0 - qc[1]*aq1 - qc[2]*aq2 - qc[3]*aq3;
        float qr1 = qc[0]*aq1 + qc[1]*aq0 + qc[2]*aq3 - qc[3]*aq2;
        float qr2 = qc[0]*aq2 - qc[1]*aq3 + qc[2]*aq0 + qc[3]*aq1;
        float qr3 = qc[0]*aq3 + qc[1]*aq2 - qc[2]*aq1 + qc[3]*aq0;
        float d[3] = {oc[4]-tr[0], oc[5]-tr[1], oc[6]-tr[2]};
        float trel[3];
        qrot(qc, d, trel);
        float* f = g_feats + (size_t)n*FEAT_ + h*SEG_ + 160;
        f[0]=qr0; f[1]=qr1; f[2]=qr2; f[3]=qr3;
        f[4]=trel[0]; f[5]=trel[1]; f[6]=trel[2]; f[7]=0.f;
    }
}

// ---------------- out init (bias) ----------------
__global__ void out_init_kernel(float* __restrict__ out, const float* __restrict__ b_out) {
    int idx = blockIdx.x*256 + threadIdx.x;
    if (idx < 512*384) out[idx] = b_out[idx % 384];
}

// ---------------- launch ----------------
extern "C" void kernel_launch(void* const* d_in, const int* in_sizes, int n_in,
                              void* d_out, int out_size) {
    const float* s    = (const float*)d_in[0];
    const float* gin  = (const float*)d_in[1];
    const float* z    = (const float*)d_in[2];
    const float* T    = (const float*)d_in[3];
    const float* mask = (const float*)d_in[4];
    const float* W_q  = (const float*)d_in[5];
    const float* b_q  = (const float*)d_in[6];
    const float* W_kv = (const float*)d_in[7];
    const float* b_kv = (const float*)d_in[8];
    const float* W_qp = (const float*)d_in[9];
    const float* b_qp = (const float*)d_in[10];
    const float* W_kp = (const float*)d_in[11];
    const float* b_kp = (const float*)d_in[12];
    const float* W_vg = (const float*)d_in[13];
    const float* b_vg = (const float*)d_in[14];
    const float* W_mg = (const float*)d_in[15];
    const float* W_b  = (const float*)d_in[16];
    const float* b_b  = (const float*)d_in[17];
    const float* W_dz = (const float*)d_in[18];
    const float* b_dz = (const float*)d_in[19];
    const float* head_weights    = (const float*)d_in[20];
    const float* softmax_weights = (const float*)d_in[21];
    const float* W_out = (const float*)d_in[22];
    const float* b_out = (const float*)d_in[23];
    const float* W_geo = (const float*)d_in[24];
    float* out = (float*)d_out;

    frames_kernel<<<2,256>>>(T, head_weights);
    pack_kernel<<<(384*PROJ_+255)/256,256>>>(W_q,W_kv,W_qp,W_kp,W_vg, b_q,b_kv,b_qp,b_kp,b_vg);
    wprep_kernel<<<20,256>>>(W_b, W_dz);

    zfuse_proj_kernel<<<1024 + 224, 256>>>(z, b_dz, s);

    pts_pack_kernel<<<512,128>>>();
    vg_kernel<<<512,128>>>(gin, W_mg);

    logits_mma<<<dim3(8,4,8), 256>>>(b_b, softmax_weights, mask);
    softmax_kernel<<<512,256>>>();

    av_opair_kernel<<<128 + 512, 256>>>();

    finalize_kernel<<<512,128>>>();

    out_init_kernel<<<768,256>>>(out, b_out);
    wout_gout_kernel<<<144 + 256, 256>>>(W_out, W_geo, out);
}

// round 15
// speedup vs baseline: 1.5564x; 1.5564x over previous
#include <cuda_runtime.h>
#include <cuda_bf16.h>
#include <math.h>
#include <stdint.h>

#define N_    512
#define H_    8
#define C_    128
#define PQ_   8
#define PV_   8
#define KF_   160
#define OC_   256
#define SEG_  312
#define FEAT_ 2496
#define PROJ_ 3584
#define NN_   ((size_t)N_*N_)

// ---------------- scratch ----------------
static __device__ float g_Wcat[384*PROJ_];
static __device__ float g_bcat[PROJ_];
static __device__ float g_proj[(size_t)N_*PROJ_];
static __device__ float g_Qf[(size_t)H_*N_*KF_];
static __device__ float g_Kf[(size_t)H_*N_*KF_];
static __device__ float g_rowc[H_*N_];
static __device__ float g_colc[H_*N_];
static __device__ float g_qn[N_*4];
static __device__ float g_tr[N_*3];
static __device__ float g_qntr[N_*8];
static __device__ float g_hw[H_];
static __device__ float g_pairb[(size_t)H_*NN_];   // [h][i][j]
static __device__ float g_zdz[(size_t)NN_*32];
static __device__ float g_A[(size_t)H_*N_*N_];
static __device__ float g_Vcat[(size_t)H_*N_*OC_];
static __device__ float g_Ocat[(size_t)H_*N_*OC_];
static __device__ float g_Orel[(size_t)H_*N_*8];
static __device__ float g_feats[(size_t)N_*FEAT_];
static __device__ __nv_bfloat16 g_Whz[40*128];
static __device__ __nv_bfloat16 g_Wlz[40*128];

// ---------------- mma helpers ----------------
__device__ __forceinline__ void mma_bf16(float* d, const uint32_t* a, const uint32_t* b) {
    asm volatile(
        "mma.sync.aligned.m16n8k16.row.col.f32.bf16.bf16.f32 "
        "{%0,%1,%2,%3}, {%4,%5,%6,%7}, {%8,%9}, {%0,%1,%2,%3};"
        : "+f"(d[0]), "+f"(d[1]), "+f"(d[2]), "+f"(d[3])
        : "r"(a[0]), "r"(a[1]), "r"(a[2]), "r"(a[3]), "r"(b[0]), "r"(b[1]));
}
__device__ __forceinline__ uint32_t packbf2(float x, float y) {
    __nv_bfloat16 hx = __float2bfloat16(x), hy = __float2bfloat16(y);
    return (uint32_t)__bfloat16_as_ushort(hx) | ((uint32_t)__bfloat16_as_ushort(hy) << 16);
}
__device__ __forceinline__ uint32_t packlo2(float x, float y) {
    float rx = x - __bfloat162float(__float2bfloat16(x));
    float ry = y - __bfloat162float(__float2bfloat16(y));
    return packbf2(rx, ry);
}
__device__ __forceinline__ void splitf(float v, uint16_t& h, uint16_t& l) {
    __nv_bfloat16 hb = __float2bfloat16(v);
    h = __bfloat16_as_ushort(hb);
    l = __bfloat16_as_ushort(__float2bfloat16(v - __bfloat162float(hb)));
}
__device__ __forceinline__ void loadA_direct(const float* Abase, int lda, int kb,
                                             uint32_t* ah, uint32_t* al) {
    float2 v0 = *(const float2*)(Abase + kb);
    float2 v1 = *(const float2*)(Abase + (size_t)8*lda + kb);
    float2 v2 = *(const float2*)(Abase + kb + 8);
    float2 v3 = *(const float2*)(Abase + (size_t)8*lda + kb + 8);
    ah[0] = packbf2(v0.x, v0.y);  al[0] = packlo2(v0.x, v0.y);
    ah[1] = packbf2(v1.x, v1.y);  al[1] = packlo2(v1.x, v1.y);
    ah[2] = packbf2(v2.x, v2.y);  al[2] = packlo2(v2.x, v2.y);
    ah[3] = packbf2(v3.x, v3.y);  al[3] = packlo2(v3.x, v3.y);
}

// shared-tile GEMM geometry (R9-proven)
#define AST 40
#define BST 40
#define AH_OFF 0
#define AL_OFF 10240
#define BH_OFF 20480
#define BL_OFF 25600
#define GSM    30720

__device__ __forceinline__ void stageA128(char* sm, const float* A, int lda, int k0, int tid) {
    #pragma unroll
    for (int i = tid*4; i < 4096; i += 1024) {
        int r = i >> 5, k = i & 31;
        float4 v = *(const float4*)(A + (size_t)r*lda + k0 + k);
        char* ph = sm + AH_OFF + (r*AST + k)*2;
        *(uint32_t*)(ph)   = packbf2(v.x, v.y);
        *(uint32_t*)(ph+4) = packbf2(v.z, v.w);
        char* pl = sm + AL_OFF + (r*AST + k)*2;
        *(uint32_t*)(pl)   = packlo2(v.x, v.y);
        *(uint32_t*)(pl+4) = packlo2(v.z, v.w);
    }
}
__device__ __forceinline__ void stageB64_nt(char* sm, const float* B, int ldb, int k0, int tid) {
    #pragma unroll
    for (int i = tid*4; i < 2048; i += 1024) {
        int n = i >> 5, k = i & 31;
        float4 v = *(const float4*)(B + (size_t)n*ldb + k0 + k);
        char* ph = sm + BH_OFF + (n*BST + k)*2;
        *(uint32_t*)(ph)   = packbf2(v.x, v.y);
        *(uint32_t*)(ph+4) = packbf2(v.z, v.w);
        char* pl = sm + BL_OFF + (n*BST + k)*2;
        *(uint32_t*)(pl)   = packlo2(v.x, v.y);
        *(uint32_t*)(pl+4) = packlo2(v.z, v.w);
    }
}
__device__ __forceinline__ void stageB64_nn(char* sm, const float* B, int ldb, int k0, int tid) {
    #pragma unroll
    for (int i = tid*4; i < 2048; i += 1024) {
        int k = i >> 6, n = i & 63;
        float4 v = *(const float4*)(B + (size_t)(k0+k)*ldb + n);
        float vv[4] = {v.x, v.y, v.z, v.w};
        #pragma unroll
        for (int j = 0; j < 4; j++) {
            uint16_t h, l; splitf(vv[j], h, l);
            *(uint16_t*)(sm + BH_OFF + ((n+j)*BST + k)*2) = h;
            *(uint16_t*)(sm + BL_OFF + ((n+j)*BST + k)*2) = l;
        }
    }
}
__device__ __forceinline__ void tile_mma(const char* sm, int warp, int lane, float (*acc)[4][4]) {
    int gid = lane >> 2, tid4 = lane & 3;
    int m0 = (warp >> 1)*32, n0 = (warp & 1)*32;
    #pragma unroll
    for (int ks = 0; ks < 2; ks++) {
        int kb = ks*16 + tid4*2;
        uint32_t ah[2][4], al[2][4];
        #pragma unroll
        for (int t = 0; t < 2; t++) {
            const char* ba = sm + AH_OFF + ((m0 + t*16 + gid)*AST + kb)*2;
            ah[t][0] = *(const uint32_t*)(ba);
            ah[t][1] = *(const uint32_t*)(ba + 8*AST*2);
            ah[t][2] = *(const uint32_t*)(ba + 16);
            ah[t][3] = *(const uint32_t*)(ba + 8*AST*2 + 16);
            const char* bal = ba + (AL_OFF - AH_OFF);
            al[t][0] = *(const uint32_t*)(bal);
            al[t][1] = *(const uint32_t*)(bal + 8*AST*2);
            al[t][2] = *(const uint32_t*)(bal + 16);
            al[t][3] = *(const uint32_t*)(bal + 8*AST*2 + 16);
        }
        #pragma unroll
        for (int u = 0; u < 4; u++) {
            const char* bb = sm + BH_OFF + ((n0 + u*8 + gid)*BST + kb)*2;
            uint32_t bh[2] = { *(const uint32_t*)bb, *(const uint32_t*)(bb+16) };
            const char* bbl = bb + (BL_OFF - BH_OFF);
            uint32_t bl2[2] = { *(const uint32_t*)bbl, *(const uint32_t*)(bbl+16) };
            #pragma unroll
            for (int t = 0; t < 2; t++) {
                mma_bf16(acc[t][u], ah[t], bh);
                mma_bf16(acc[t][u], al[t], bh);
                mma_bf16(acc[t][u], ah[t], bl2);
            }
        }
    }
}

// ---------------- misc helpers ----------------
__device__ __forceinline__ void qrot(const float* q, const float* v, float* o) {
    float w=q[0], x=q[1], y=q[2], z=q[3];
    float uvx = y*v[2]-z*v[1];
    float uvy = z*v[0]-x*v[2];
    float uvz = x*v[1]-y*v[0];
    float uuvx = y*uvz-z*uvy;
    float uuvy = z*uvx-x*uvz;
    float uuvz = x*uvy-y*uvx;
    o[0]=v[0]+2.f*(w*uvx+uuvx);
    o[1]=v[1]+2.f*(w*uvy+uuvy);
    o[2]=v[2]+2.f*(w*uvz+uuvz);
}

// ---------------- frames + head weights + zfuse W prep (merged tiny setup) ----------------
__global__ void setup_kernel(const float* __restrict__ T, const float* __restrict__ head_weights,
                             const float* __restrict__ W_b, const float* __restrict__ W_dz) {
    int idx = blockIdx.x*256 + threadIdx.x;
    if (idx < N_) {
        int n = idx;
        const float* t = T + n*16;
        float q0=t[0], q1=t[1], q2=t[2], q3=t[3];
        float inv = rsqrtf(q0*q0+q1*q1+q2*q2+q3*q3 + 1e-8f);
        g_qn[n*4+0]=q0*inv; g_qn[n*4+1]=q1*inv; g_qn[n*4+2]=q2*inv; g_qn[n*4+3]=q3*inv;
        g_tr[n*3+0]=t[4]; g_tr[n*3+1]=t[5]; g_tr[n*3+2]=t[6];
        g_qntr[n*8+0]=q0*inv; g_qntr[n*8+1]=q1*inv; g_qntr[n*8+2]=q2*inv; g_qntr[n*8+3]=q3*inv;
        g_qntr[n*8+4]=t[4]; g_qntr[n*8+5]=t[5]; g_qntr[n*8+6]=t[6]; g_qntr[n*8+7]=0.f;
        if (n < H_) {
            float x = head_weights[n];
            float sp = (x > 20.f) ? x : log1pf(expf(x));
            g_hw[n] = sp * rsqrtf(108.0f);
        }
    } else {
        int w = idx - N_;
        if (w < 40*128) {
            int n = w >> 7, k = w & 127;
            float v = (n < 8) ? W_b[k*8 + n] : W_dz[k*32 + (n-8)];
            __nv_bfloat16 h = __float2bfloat16(v);
            g_Whz[w] = h;
            g_Wlz[w] = __float2bfloat16(v - __bfloat162float(h));
        }
    }
}

// ---------------- zfuse (R9-proven) ----------------
#define ZWST 272
__global__ void __launch_bounds__(256) zfuse_mma(const float* __restrict__ z,
                                                 const float* __restrict__ b_dz) {
    __shared__ __align__(16) char sm[2*40*ZWST];
    int tid = threadIdx.x;
    int warp = tid >> 5, lane = tid & 31;
    int gid = lane >> 2, tid4 = lane & 3;
    {
        const uint32_t* wh32 = (const uint32_t*)g_Whz;
        const uint32_t* wl32 = (const uint32_t*)g_Wlz;
        for (int i = tid; i < 40*64; i += 256) {
            int n = i >> 6, kw = i & 63;
            *(uint32_t*)(sm + n*ZWST + kw*4)           = wh32[i];
            *(uint32_t*)(sm + 40*ZWST + n*ZWST + kw*4) = wl32[i];
        }
    }
    __syncthreads();

    size_t p0 = (size_t)blockIdx.x * 256;
    const float* zb = z + (p0 + warp*32 + gid)*128;

    float acc[2][5][4] = {};
    #pragma unroll
    for (int ks = 0; ks < 8; ks++) {
        int kb = ks*16 + tid4*2;
        uint32_t ah[2][4], al[2][4];
        #pragma unroll
        for (int t = 0; t < 2; t++)
            loadA_direct(zb + (size_t)t*16*128, 128, kb, ah[t], al[t]);
        #pragma unroll
        for (int nt = 0; nt < 5; nt++) {
            int ob = (nt*8 + gid)*ZWST + kb*2;
            uint32_t bh[2], bl[2];
            bh[0] = *(const uint32_t*)(sm + ob);
            bh[1] = *(const uint32_t*)(sm + ob + 16);
            bl[0] = *(const uint32_t*)(sm + 40*ZWST + ob);
            bl[1] = *(const uint32_t*)(sm + 40*ZWST + ob + 16);
            #pragma unroll
            for (int t = 0; t < 2; t++) {
                mma_bf16(acc[t][nt], ah[t], bh);
                mma_bf16(acc[t][nt], al[t], bh);
                mma_bf16(acc[t][nt], ah[t], bl);
            }
        }
    }

    float bz[8];
    #pragma unroll
    for (int nt = 1; nt < 5; nt++) {
        int zc = nt*8 + tid4*2 - 8;
        bz[(nt-1)*2]   = b_dz[zc];
        bz[(nt-1)*2+1] = b_dz[zc+1];
    }
    #pragma unroll
    for (int t = 0; t < 2; t++) {
        size_t r0 = p0 + warp*32 + t*16 + gid;
        size_t r1 = r0 + 8;
        int c0 = tid4*2;
        g_pairb[(size_t)(c0  )*NN_ + r0] = acc[t][0][0];
        g_pairb[(size_t)(c0+1)*NN_ + r0] = acc[t][0][1];
        g_pairb[(size_t)(c0  )*NN_ + r1] = acc[t][0][2];
        g_pairb[(size_t)(c0+1)*NN_ + r1] = acc[t][0][3];
        #pragma unroll
        for (int nt = 1; nt < 5; nt++) {
            int zc = nt*8 + tid4*2 - 8;
            float bz0 = bz[(nt-1)*2], bz1 = bz[(nt-1)*2+1];
            *(float2*)(g_zdz + r0*32 + zc) = make_float2(acc[t][nt][0] + bz0, acc[t][nt][1] + bz1);
            *(float2*)(g_zdz + r1*32 + zc) = make_float2(acc[t][nt][2] + bz0, acc[t][nt][3] + bz1);
        }
    }
}

// ---------------- weight packing ----------------
__global__ void pack_kernel(const float* __restrict__ W_q, const float* __restrict__ W_kv,
                            const float* __restrict__ W_qp, const float* __restrict__ W_kp,
                            const float* __restrict__ W_vg,
                            const float* __restrict__ b_q, const float* __restrict__ b_kv,
                            const float* __restrict__ b_qp, const float* __restrict__ b_kp,
                            const float* __restrict__ b_vg) {
    int idx = blockIdx.x*256 + threadIdx.x;
    if (idx >= 384*PROJ_) return;
    int k = idx / PROJ_, c = idx % PROJ_;
    float v;
    if      (c < 1024) v = W_q [k*1024 + c];
    else if (c < 3072) v = W_kv[k*2048 + (c-1024)];
    else if (c < 3264) v = W_qp[k*192  + (c-3072)];
    else if (c < 3456) v = W_kp[k*192  + (c-3264)];
    else               v = W_vg[k*128  + (c-3456)];
    g_Wcat[idx] = v;
    if (k == 0) {
        float b;
        if      (c < 1024) b = b_q [c];
        else if (c < 3072) b = b_kv[c-1024];
        else if (c < 3264) b = b_qp[c-3072];
        else if (c < 3456) b = b_kp[c-3264];
        else               b = b_vg[c-3456];
        g_bcat[c] = b;
    }
}

// ---------------- proj: s[512,384] @ Wcat[384,3584] + bias (R9 staged) ----------------
__global__ void __launch_bounds__(256) proj_mma(const float* __restrict__ s) {
    __shared__ __align__(16) char sm[GSM];
    int tid = threadIdx.x, warp = tid >> 5, lane = tid & 31;
    int rowBase = blockIdx.y*128, nBase = blockIdx.x*64;
    const float* A = s + (size_t)rowBase*384;
    const float* B = g_Wcat + nBase;
    float acc[2][4][4] = {};
    for (int k0 = 0; k0 < 384; k0 += 32) {
        __syncthreads();
        stageA128(sm, A, 384, k0, tid);
        stageB64_nn(sm, B, PROJ_, k0, tid);
        __syncthreads();
        tile_mma(sm, warp, lane, acc);
    }
    int gid = lane >> 2, tid4 = lane & 3;
    int m0 = (warp >> 1)*32, n0w = (warp & 1)*32;
    #pragma unroll
    for (int t = 0; t < 2; t++) {
        int r0 = rowBase + m0 + t*16 + gid;
        #pragma unroll
        for (int u = 0; u < 4; u++) {
            int c = nBase + n0w + u*8 + tid4*2;
            float b0 = g_bcat[c], b1 = g_bcat[c+1];
            *(float2*)(g_proj + (size_t)r0*PROJ_ + c)     = make_float2(acc[t][u][0]+b0, acc[t][u][1]+b1);
            *(float2*)(g_proj + (size_t)(r0+8)*PROJ_ + c) = make_float2(acc[t][u][2]+b0, acc[t][u][3]+b1);
        }
    }
}

// ---------------- logits (R9 staged) ----------------
__global__ void __launch_bounds__(256) logits_mma(const float* __restrict__ b_b,
                                                  const float* __restrict__ sw,
                                                  const float* __restrict__ mask) {
    __shared__ __align__(16) char sm[GSM];
    int tid = threadIdx.x, warp = tid >> 5, lane = tid & 31;
    int h = blockIdx.z;
    int rowBase = blockIdx.y*128, nBase = blockIdx.x*64;
    const float* A = g_Qf + ((size_t)h*N_ + rowBase)*KF_;
    const float* B = g_Kf + ((size_t)h*N_ + nBase)*KF_;
    float acc[2][4][4] = {};
    for (int k0 = 0; k0 < KF_; k0 += 32) {
        __syncthreads();
        stageA128(sm, A, KF_, k0, tid);
        stageB64_nt(sm, B, KF_, k0, tid);
        __syncthreads();
        tile_mma(sm, warp, lane, acc);
    }
    const float s2 = 0.57735026918962576f;
    float swh = sw[h], bbh = b_b[h];
    const float* pbh = g_pairb + (size_t)h*NN_;
    int gid = lane >> 2, tid4 = lane & 3;
    int m0 = (warp >> 1)*32, n0w = (warp & 1)*32;
    #pragma unroll
    for (int t = 0; t < 2; t++) {
        int gi0 = rowBase + m0 + t*16 + gid;
        int gi1 = gi0 + 8;
        float rc0 = g_rowc[h*N_+gi0], rc1 = g_rowc[h*N_+gi1];
        float mi0 = mask[gi0], mi1 = mask[gi1];
        #pragma unroll
        for (int u = 0; u < 4; u++) {
            int gc = nBase + n0w + u*8 + tid4*2;
            float2 pb0 = *(const float2*)(pbh + (size_t)gi0*N_ + gc);
            float2 pb1 = *(const float2*)(pbh + (size_t)gi1*N_ + gc);
            #pragma unroll
            for (int j = 0; j < 2; j++) {
                int c = gc + j;
                float cc = g_colc[h*N_+c], mj = mask[c];
                float p0 = j ? pb0.y : pb0.x;
                float p1 = j ? pb1.y : pb1.x;
                float v0 = acc[t][u][j]   + rc0 + cc + s2*(p0+bbh) + 100000.0f*(mi0*mj-1.0f);
                float v1 = acc[t][u][2+j] + rc1 + cc + s2*(p1+bbh) + 100000.0f*(mi1*mj-1.0f);
                g_A[((size_t)h*N_+gi0)*N_ + c] = v0*swh;
                g_A[((size_t)h*N_+gi1)*N_ + c] = v1*swh;
            }
        }
    }
}

// ---------------- av (R9 staged) ----------------
__global__ void __launch_bounds__(256) av_mma() {
    __shared__ __align__(16) char sm[GSM];
    int tid = threadIdx.x, warp = tid >> 5, lane = tid & 31;
    int h = blockIdx.z;
    int rowBase = blockIdx.y*128, nBase = blockIdx.x*64;
    const float* A = g_A + ((size_t)h*N_ + rowBase)*N_;
    const float* B = g_Vcat + (size_t)h*N_*OC_ + nBase;
    float acc[2][4][4] = {};
    for (int k0 = 0; k0 < N_; k0 += 32) {
        __syncthreads();
        stageA128(sm, A, N_, k0, tid);
        stageB64_nn(sm, B, OC_, k0, tid);
        __syncthreads();
        tile_mma(sm, warp, lane, acc);
    }
    int gid = lane >> 2, tid4 = lane & 3;
    int m0 = (warp >> 1)*32, n0w = (warp & 1)*32;
    #pragma unroll
    for (int t = 0; t < 2; t++) {
        int r0 = rowBase + m0 + t*16 + gid;
        #pragma unroll
        for (int u = 0; u < 4; u++) {
            int c = nBase + n0w + u*8 + tid4*2;
            *(float2*)(g_Ocat + ((size_t)h*N_ + r0)*OC_ + c)   = make_float2(acc[t][u][0], acc[t][u][1]);
            *(float2*)(g_Ocat + ((size_t)h*N_ + r0+8)*OC_ + c) = make_float2(acc[t][u][2], acc[t][u][3]);
        }
    }
}

// ---------------- wout (R9 staged, split-K 6) ----------------
__global__ void __launch_bounds__(256) wout_mma(const float* __restrict__ W_out,
                                                float* __restrict__ out) {
    __shared__ __align__(16) char sm[GSM];
    int tid = threadIdx.x, warp = tid >> 5, lane = tid & 31;
    int rowBase = blockIdx.y*128, nBase = blockIdx.x*64;
    int kstart = blockIdx.z * 416;
    const float* A = g_feats + (size_t)rowBase*FEAT_;
    const float* B = W_out + nBase;
    float acc[2][4][4] = {};
    for (int k0 = kstart; k0 < kstart + 416; k0 += 32) {
        __syncthreads();
        stageA128(sm, A, FEAT_, k0, tid);
        stageB64_nn(sm, B, 384, k0, tid);
        __syncthreads();
        tile_mma(sm, warp, lane, acc);
    }
    int gid = lane >> 2, tid4 = lane & 3;
    int m0 = (warp >> 1)*32, n0w = (warp & 1)*32;
    #pragma unroll
    for (int t = 0; t < 2; t++) {
        int r0 = rowBase + m0 + t*16 + gid;
        #pragma unroll
        for (int u = 0; u < 4; u++) {
            int c = nBase + n0w + u*8 + tid4*2;
            atomicAdd(&out[(size_t)r0*384 + c],       acc[t][u][0]);
            atomicAdd(&out[(size_t)r0*384 + c + 1],   acc[t][u][1]);
            atomicAdd(&out[(size_t)(r0+8)*384 + c],   acc[t][u][2]);
            atomicAdd(&out[(size_t)(r0+8)*384 + c+1], acc[t][u][3]);
        }
    }
}

// ---------------- point transforms + Qf/Kf packing ----------------
__global__ void pts_pack_kernel() {
    int n = blockIdx.x, tid = threadIdx.x;   // 128 threads
    __shared__ float sq[64*3], sk[64*3];
    __shared__ float qsq[H_], ksq[H_];
    __shared__ float qn[4], tr[3];
    if (tid<4) qn[tid]=g_qn[n*4+tid];
    if (tid>=4 && tid<7) tr[tid-4]=g_tr[n*3+tid-4];
    if (tid<H_) { qsq[tid]=0.f; ksq[tid]=0.f; }
    __syncthreads();
    if (tid < 64) {
        float p[3], o[3];
        #pragma unroll
        for (int d=0; d<3; d++) p[d]=g_proj[(size_t)n*PROJ_ + 3072 + d*64 + tid];
        qrot(qn, p, o);
        float ss=0.f;
        #pragma unroll
        for (int d=0; d<3; d++) { o[d]+=tr[d]; sq[tid*3+d]=o[d]; ss+=o[d]*o[d]; }
        atomicAdd(&qsq[tid>>3], ss);
        #pragma unroll
        for (int d=0; d<3; d++) p[d]=g_proj[(size_t)n*PROJ_ + 3264 + d*64 + tid];
        qrot(qn, p, o);
        ss=0.f;
        #pragma unroll
        for (int d=0; d<3; d++) { o[d]+=tr[d]; sk[tid*3+d]=o[d]; ss+=o[d]*o[d]; }
        atomicAdd(&ksq[tid>>3], ss);
    }
    __syncthreads();
    float s1 = rsqrtf(384.f);
    for (int t=tid; t<H_*KF_; t+=128) {
        int h=t/KF_, c=t%KF_;
        float qv, kv;
        if (c < C_) {
            qv = g_proj[(size_t)n*PROJ_ + h*C_ + c] * s1;
            kv = g_proj[(size_t)n*PROJ_ + 1024 + h*256 + c];
        } else if (c < 152) {
            int m=c-128, pp=m/3, d=m%3;
            int idx=(h*PQ_+pp)*3+d;
            qv = sq[idx]*g_hw[h];
            kv = sk[idx];
        } else { qv=0.f; kv=0.f; }
        g_Qf[((size_t)h*N_+n)*KF_ + c] = qv;
        g_Kf[((size_t)h*N_+n)*KF_ + c] = kv;
    }
    if (tid < H_) {
        g_rowc[tid*N_+n] = -0.5f*g_hw[tid]*qsq[tid];
        g_colc[tid*N_+n] = -0.5f*g_hw[tid]*ksq[tid];
    }
}

// ---------------- v_g mix + mv_transform + Vcat assembly ----------------
__global__ void vg_kernel(const float* __restrict__ gin, const float* __restrict__ W_mg) {
    int n = blockIdx.x, tid = threadIdx.x;   // 128 threads
    __shared__ float cat16[16*16];
    __shared__ float mix[64*16];
    __shared__ float qn[4], tr[3];
    if (tid<4) qn[tid]=g_qn[n*4+tid];
    if (tid>=4 && tid<7) tr[tid-4]=g_tr[n*3+tid-4];
    {
        int p=tid>>4, c=tid&15;
        cat16[p*16+c]     = g_proj[(size_t)n*PROJ_ + 3456 + p*16 + c];
        cat16[(p+8)*16+c] = gin  [(size_t)n*128 + p*16 + c];
    }
    __syncthreads();
    for (int t=tid; t<1024; t+=128) {
        int o=t>>4, c=t&15;
        float acc=0.f;
        #pragma unroll
        for (int i=0;i<16;i++) acc += W_mg[o*16+i]*cat16[i*16+c];
        mix[t]=acc;
    }
    __syncthreads();
    if (tid < 64) {
        int o=tid, h=o>>3, p=o&7;
        float mv[16];
        #pragma unroll
        for (int c=0;c<16;c++) mv[c]=mix[o*16+c];
        float out[16];
        out[0]=mv[0];
        qrot(qn, mv+1, out+1);
        qrot(qn, mv+4, out+4);
        float pv[3]; qrot(qn, mv+7, pv);
        float w=mv[10];
        out[7]=pv[0]+w*tr[0]; out[8]=pv[1]+w*tr[1]; out[9]=pv[2]+w*tr[2];
        #pragma unroll
        for (int c=10;c<16;c++) out[c]=mv[c];
        float* dst = g_Vcat + ((size_t)h*N_+n)*OC_ + 128 + p*16;
        #pragma unroll
        for (int c=0;c<16;c++) dst[c]=out[c];
    }
    for (int t=tid; t<H_*C_; t+=128) {
        int h=t>>7, c=t&127;
        g_Vcat[((size_t)h*N_+n)*OC_ + c] = g_proj[(size_t)n*PROJ_ + 1024 + h*256 + 128 + c];
    }
}

// ---------------- row softmax + fused o_rel accumulation ----------------
__global__ void __launch_bounds__(256) softmax_kernel() {
    __shared__ float qt[512*9];
    int tid = threadIdx.x;
    int warp = tid >> 5, lane = tid & 31;
    for (int t = tid; t < 512; t += 256) {
        #pragma unroll
        for (int c=0;c<8;c++) qt[t*9+c] = g_qntr[t*8+c];
    }
    __syncthreads();
    int row = blockIdx.x*8 + warp;
    float* a = g_A + (size_t)row*N_;
    float v[16];
    #pragma unroll
    for (int t=0;t<16;t++) v[t] = a[lane + 32*t];
    float m = v[0];
    #pragma unroll
    for (int t=1;t<16;t++) m = fmaxf(m, v[t]);
    #pragma unroll
    for (int off=16; off>0; off>>=1) m = fmaxf(m, __shfl_xor_sync(0xffffffff, m, off));
    float s = 0.f;
    #pragma unroll
    for (int t=0;t<16;t++) { v[t] = expf(v[t]-m); s += v[t]; }
    #pragma unroll
    for (int off=16; off>0; off>>=1) s += __shfl_xor_sync(0xffffffff, s, off);
    float inv = 1.f/s;
    float orel[8] = {};
    #pragma unroll
    for (int t=0;t<16;t++) {
        float p = v[t]*inv;
        a[lane + 32*t] = p;
        const float* q = qt + (lane + 32*t)*9;
        #pragma unroll
        for (int c=0;c<8;c++) orel[c] += p*q[c];
    }
    #pragma unroll
    for (int c=0;c<8;c++) {
        #pragma unroll
        for (int off=16; off>0; off>>=1)
            orel[c] += __shfl_xor_sync(0xffffffff, orel[c], off);
    }
    if (lane == 0) {
        #pragma unroll
        for (int c=0;c<8;c++) g_Orel[(size_t)row*8+c] = orel[c];
    }
}

// ---------------- o_pair (R9 staged) ----------------
__global__ void opair_kernel() {
    int i = blockIdx.x;
    int tid = threadIdx.x;  // 256
    __shared__ float Zs[64*33];
    __shared__ float Asm[8*64];
    int hh = tid>>5, cc = tid&31;
    float acc = 0.f;
    for (int jt=0; jt<N_; jt+=64) {
        __syncthreads();
        for (int t=tid; t<2048; t+=256) {
            int jj=t>>5, c=t&31;
            Zs[jj*33+c] = g_zdz[((size_t)i*N_ + jt+jj)*32 + c];
        }
        for (int t=tid; t<512; t+=256) {
            int h=t>>6, jj=t&63;
            Asm[h*64+jj] = g_A[((size_t)h*N_+i)*N_ + jt+jj];
        }
        __syncthreads();
        #pragma unroll
        for (int jj=0; jj<64; jj++) acc += Asm[hh*64+jj]*Zs[jj*33+cc];
    }
    g_feats[(size_t)i*FEAT_ + hh*SEG_ + cc] = acc;
}

// ---------------- finalize ----------------
__global__ void finalize_kernel() {
    int n = blockIdx.x, tid = threadIdx.x;  // 128
    __shared__ float qn[4], tr[3];
    if (tid<4) qn[tid]=g_qn[n*4+tid];
    if (tid>=4 && tid<7) tr[tid-4]=g_tr[n*3+tid-4];
    __syncthreads();
    for (int t=tid; t<H_*C_; t+=128) {
        int h=t>>7, c=t&127;
        g_feats[(size_t)n*FEAT_ + h*SEG_ + 32 + c] = g_Ocat[((size_t)h*N_+n)*OC_ + c];
    }
    if (tid < 64) {
        int h=tid>>3, p=tid&7;
        const float* oc = g_Ocat + ((size_t)h*N_+n)*OC_ + 128 + p*16;
        float mv[16];
        #pragma unroll
        for (int c=0;c<16;c++) mv[c]=oc[c];
        float qc[4] = {qn[0], -qn[1], -qn[2], -qn[3]};
        float out[16];
        out[0]=mv[0];
        qrot(qc, mv+1, out+1);
        qrot(qc, mv+4, out+4);
        float w=mv[10];
        float tmp[3] = {mv[7]-w*tr[0], mv[8]-w*tr[1], mv[9]-w*tr[2]};
        qrot(qc, tmp, out+7);
        #pragma unroll
        for (int c=10;c<16;c++) out[c]=mv[c];
        float s1v=1e-8f, s2v=1e-8f;
        #pragma unroll
        for (int c=0;c<10;c++) s1v += out[c]*out[c];
        #pragma unroll
        for (int c=10;c<16;c++) s2v += out[c]*out[c];
        float* f = g_feats + (size_t)n*FEAT_ + h*SEG_;
        #pragma unroll
        for (int c=0;c<16;c++) f[168+p*16+c]=out[c];
        f[296+p*2+0]=sqrtf(s1v);
        f[296+p*2+1]=sqrtf(s2v);
    }
    if (tid < H_) {
        int h=tid;
        const float* oc = g_Orel + ((size_t)h*N_+n)*8;
        float aq0=oc[0], aq1=oc[1], aq2=oc[2], aq3=oc[3];
        float qc[4] = {qn[0], -qn[1], -qn[2], -qn[3]};
        float qr0 = qc[0]*aq0 - qc[1]*aq1 - qc[2]*aq2 - qc[3]*aq3;
        float qr1 = qc[0]*aq1 + qc[1]*aq0 + qc[2]*aq3 - qc[3]*aq2;
        float qr2 = qc[0]*aq2 - qc[1]*aq3 + qc[2]*aq0 + qc[3]*aq1;
        float qr3 = qc[0]*aq3 + qc[1]*aq2 - qc[2]*aq1 + qc[3]*aq0;
        float d[3] = {oc[4]-tr[0], oc[5]-tr[1], oc[6]-tr[2]};
        float trel[3];
        qrot(qc, d, trel);
        float* f = g_feats + (size_t)n*FEAT_ + h*SEG_ + 160;
        f[0]=qr0; f[1]=qr1; f[2]=qr2; f[3]=qr3;
        f[4]=trel[0]; f[5]=trel[1]; f[6]=trel[2]; f[7]=0.f;
    }
}

// ---------------- out init (bias) ----------------
__global__ void out_init_kernel(float* __restrict__ out, const float* __restrict__ b_out) {
    int idx = blockIdx.x*256 + threadIdx.x;
    if (idx < 512*384) out[idx] = b_out[idx % 384];
}

// ---------------- g_out ----------------
__global__ void gout_kernel(const float* __restrict__ W_geo, float* __restrict__ out) {
    int n = blockIdx.x, tid = threadIdx.x;  // 128
    int o = tid>>4, c = tid&15;
    float acc = 0.f;
    #pragma unroll
    for (int i2=0; i2<64; i2++) {
        acc += W_geo[o*64+i2] * g_feats[(size_t)n*FEAT_ + (i2>>3)*SEG_ + 168 + (i2&7)*16 + c];
    }
    out[(size_t)n*128 + o*16 + c] = acc;
}

// ---------------- launch ----------------
extern "C" void kernel_launch(void* const* d_in, const int* in_sizes, int n_in,
                              void* d_out, int out_size) {
    const float* s    = (const float*)d_in[0];
    const float* gin  = (const float*)d_in[1];
    const float* z    = (const float*)d_in[2];
    const float* T    = (const float*)d_in[3];
    const float* mask = (const float*)d_in[4];
    const float* W_q  = (const float*)d_in[5];
    const float* b_q  = (const float*)d_in[6];
    const float* W_kv = (const float*)d_in[7];
    const float* b_kv = (const float*)d_in[8];
    const float* W_qp = (const float*)d_in[9];
    const float* b_qp = (const float*)d_in[10];
    const float* W_kp = (const float*)d_in[11];
    const float* b_kp = (const float*)d_in[12];
    const float* W_vg = (const float*)d_in[13];
    const float* b_vg = (const float*)d_in[14];
    const float* W_mg = (const float*)d_in[15];
    const float* W_b  = (const float*)d_in[16];
    const float* b_b  = (const float*)d_in[17];
    const float* W_dz = (const float*)d_in[18];
    const float* b_dz = (const float*)d_in[19];
    const float* head_weights    = (const float*)d_in[20];
    const float* softmax_weights = (const float*)d_in[21];
    const float* W_out = (const float*)d_in[22];
    const float* b_out = (const float*)d_in[23];
    const float* W_geo = (const float*)d_in[24];
    float* out = (float*)d_out;

    setup_kernel<<<(N_ + 40*128 + 255)/256, 256>>>(T, head_weights, W_b, W_dz);
    pack_kernel<<<(384*PROJ_+255)/256,256>>>(W_q,W_kv,W_qp,W_kp,W_vg, b_q,b_kv,b_qp,b_kp,b_vg);
    zfuse_mma<<<1024,256>>>(z, b_dz);

    proj_mma<<<dim3(PROJ_/64, 4), 256>>>(s);

    pts_pack_kernel<<<512,128>>>();
    vg_kernel<<<512,128>>>(gin, W_mg);

    logits_mma<<<dim3(8,4,8), 256>>>(b_b, softmax_weights, mask);
    softmax_kernel<<<512,256>>>();
    av_mma<<<dim3(4,4,8), 256>>>();
    opair_kernel<<<512,256>>>();
    finalize_kernel<<<512,128>>>();

    out_init_kernel<<<768,256>>>(out, b_out);
    wout_mma<<<dim3(6,4,6), 256>>>(W_out, out);
    gout_kernel<<<512,128>>>(W_geo, out + 512*384);
}

// round 16
// speedup vs baseline: 1.6115x; 1.0354x over previous
#include <cuda_runtime.h>
#include <cuda_bf16.h>
#include <math.h>
#include <stdint.h>

#define N_    512
#define H_    8
#define C_    128
#define PQ_   8
#define PV_   8
#define KF_   160
#define OC_   256
#define SEG_  312
#define FEAT_ 2496
#define PROJ_ 3584
#define NN_   ((size_t)N_*N_)

// ---------------- scratch ----------------
static __device__ float g_Wcat[384*PROJ_];
static __device__ float g_bcat[PROJ_];
static __device__ float g_proj[(size_t)N_*PROJ_];
static __device__ float g_Qf[(size_t)H_*N_*KF_];
static __device__ float g_Kf[(size_t)H_*N_*KF_];
static __device__ float g_rowc[H_*N_];
static __device__ float g_colc[H_*N_];
static __device__ float g_qn[N_*4];
static __device__ float g_tr[N_*3];
static __device__ float g_qntr[N_*8];
static __device__ float g_hw[H_];
static __device__ float g_pairb[(size_t)H_*NN_];   // [h][i][j]
static __device__ float g_zdz[(size_t)NN_*32];
static __device__ float g_A[(size_t)H_*N_*N_];
static __device__ float g_Vcat[(size_t)H_*N_*OC_];
static __device__ float g_Ocat[(size_t)H_*N_*OC_];
static __device__ float g_Orel[(size_t)H_*N_*8];
static __device__ float g_feats[(size_t)N_*FEAT_];
static __device__ __nv_bfloat16 g_Whz[40*128];
static __device__ __nv_bfloat16 g_Wlz[40*128];

// ---------------- mma helpers ----------------
__device__ __forceinline__ void mma_bf16(float* d, const uint32_t* a, const uint32_t* b) {
    asm volatile(
        "mma.sync.aligned.m16n8k16.row.col.f32.bf16.bf16.f32 "
        "{%0,%1,%2,%3}, {%4,%5,%6,%7}, {%8,%9}, {%0,%1,%2,%3};"
        : "+f"(d[0]), "+f"(d[1]), "+f"(d[2]), "+f"(d[3])
        : "r"(a[0]), "r"(a[1]), "r"(a[2]), "r"(a[3]), "r"(b[0]), "r"(b[1]));
}
__device__ __forceinline__ uint32_t packbf2(float x, float y) {
    __nv_bfloat16 hx = __float2bfloat16(x), hy = __float2bfloat16(y);
    return (uint32_t)__bfloat16_as_ushort(hx) | ((uint32_t)__bfloat16_as_ushort(hy) << 16);
}
__device__ __forceinline__ uint32_t packlo2(float x, float y) {
    float rx = x - __bfloat162float(__float2bfloat16(x));
    float ry = y - __bfloat162float(__float2bfloat16(y));
    return packbf2(rx, ry);
}
__device__ __forceinline__ void splitf(float v, uint16_t& h, uint16_t& l) {
    __nv_bfloat16 hb = __float2bfloat16(v);
    h = __bfloat16_as_ushort(hb);
    l = __bfloat16_as_ushort(__float2bfloat16(v - __bfloat162float(hb)));
}
__device__ __forceinline__ void loadA_direct(const float* Abase, int lda, int kb,
                                             uint32_t* ah, uint32_t* al) {
    float2 v0 = *(const float2*)(Abase + kb);
    float2 v1 = *(const float2*)(Abase + (size_t)8*lda + kb);
    float2 v2 = *(const float2*)(Abase + kb + 8);
    float2 v3 = *(const float2*)(Abase + (size_t)8*lda + kb + 8);
    ah[0] = packbf2(v0.x, v0.y);  al[0] = packlo2(v0.x, v0.y);
    ah[1] = packbf2(v1.x, v1.y);  al[1] = packlo2(v1.x, v1.y);
    ah[2] = packbf2(v2.x, v2.y);  al[2] = packlo2(v2.x, v2.y);
    ah[3] = packbf2(v3.x, v3.y);  al[3] = packlo2(v3.x, v3.y);
}

// shared-tile GEMM geometry (R9-proven)
#define AST 40
#define BST 40
#define AH_OFF 0
#define AL_OFF 10240
#define BH_OFF 20480
#define BL_OFF 25600
#define GSM    30720

// ---- register prefetch / store (software pipeline) ----
__device__ __forceinline__ void pfA(const float* A, int lda, int k0, int tid, float4* ra) {
    #pragma unroll
    for (int j = 0; j < 4; j++) {
        int i = tid*4 + j*1024;
        ra[j] = *(const float4*)(A + (size_t)(i>>5)*lda + k0 + (i&31));
    }
}
__device__ __forceinline__ void stA(char* sm, const float4* ra, int tid) {
    #pragma unroll
    for (int j = 0; j < 4; j++) {
        int i = tid*4 + j*1024;
        int r = i>>5, k = i&31;
        float4 v = ra[j];
        char* ph = sm + AH_OFF + (r*AST + k)*2;
        *(uint32_t*)(ph)   = packbf2(v.x, v.y);
        *(uint32_t*)(ph+4) = packbf2(v.z, v.w);
        char* pl = sm + AL_OFF + (r*AST + k)*2;
        *(uint32_t*)(pl)   = packlo2(v.x, v.y);
        *(uint32_t*)(pl+4) = packlo2(v.z, v.w);
    }
}
__device__ __forceinline__ void pfB_nn(const float* B, int ldb, int k0, int tid, float4* rb) {
    #pragma unroll
    for (int j = 0; j < 2; j++) {
        int i = tid*4 + j*1024;
        int k = i>>6, n = i&63;
        rb[j] = *(const float4*)(B + (size_t)(k0+k)*ldb + n);
    }
}
__device__ __forceinline__ void stB_nn(char* sm, const float4* rb, int tid) {
    #pragma unroll
    for (int j = 0; j < 2; j++) {
        int i = tid*4 + j*1024;
        int k = i>>6, n = i&63;
        float vv[4] = {rb[j].x, rb[j].y, rb[j].z, rb[j].w};
        #pragma unroll
        for (int jj = 0; jj < 4; jj++) {
            uint16_t h, l; splitf(vv[jj], h, l);
            *(uint16_t*)(sm + BH_OFF + ((n+jj)*BST + k)*2) = h;
            *(uint16_t*)(sm + BL_OFF + ((n+jj)*BST + k)*2) = l;
        }
    }
}
__device__ __forceinline__ void pfB_nt(const float* B, int ldb, int k0, int tid, float4* rb) {
    #pragma unroll
    for (int j = 0; j < 2; j++) {
        int i = tid*4 + j*1024;
        int n = i>>5, k = i&31;
        rb[j] = *(const float4*)(B + (size_t)n*ldb + k0 + k);
    }
}
__device__ __forceinline__ void stB_nt(char* sm, const float4* rb, int tid) {
    #pragma unroll
    for (int j = 0; j < 2; j++) {
        int i = tid*4 + j*1024;
        int n = i>>5, k = i&31;
        float4 v = rb[j];
        char* ph = sm + BH_OFF + (n*BST + k)*2;
        *(uint32_t*)(ph)   = packbf2(v.x, v.y);
        *(uint32_t*)(ph+4) = packbf2(v.z, v.w);
        char* pl = sm + BL_OFF + (n*BST + k)*2;
        *(uint32_t*)(pl)   = packlo2(v.x, v.y);
        *(uint32_t*)(pl+4) = packlo2(v.z, v.w);
    }
}
__device__ __forceinline__ void tile_mma(const char* sm, int warp, int lane, float (*acc)[4][4]) {
    int gid = lane >> 2, tid4 = lane & 3;
    int m0 = (warp >> 1)*32, n0 = (warp & 1)*32;
    #pragma unroll
    for (int ks = 0; ks < 2; ks++) {
        int kb = ks*16 + tid4*2;
        uint32_t ah[2][4], al[2][4];
        #pragma unroll
        for (int t = 0; t < 2; t++) {
            const char* ba = sm + AH_OFF + ((m0 + t*16 + gid)*AST + kb)*2;
            ah[t][0] = *(const uint32_t*)(ba);
            ah[t][1] = *(const uint32_t*)(ba + 8*AST*2);
            ah[t][2] = *(const uint32_t*)(ba + 16);
            ah[t][3] = *(const uint32_t*)(ba + 8*AST*2 + 16);
            const char* bal = ba + (AL_OFF - AH_OFF);
            al[t][0] = *(const uint32_t*)(bal);
            al[t][1] = *(const uint32_t*)(bal + 8*AST*2);
            al[t][2] = *(const uint32_t*)(bal + 16);
            al[t][3] = *(const uint32_t*)(bal + 8*AST*2 + 16);
        }
        #pragma unroll
        for (int u = 0; u < 4; u++) {
            const char* bb = sm + BH_OFF + ((n0 + u*8 + gid)*BST + kb)*2;
            uint32_t bh[2] = { *(const uint32_t*)bb, *(const uint32_t*)(bb+16) };
            const char* bbl = bb + (BL_OFF - BH_OFF);
            uint32_t bl2[2] = { *(const uint32_t*)bbl, *(const uint32_t*)(bbl+16) };
            #pragma unroll
            for (int t = 0; t < 2; t++) {
                mma_bf16(acc[t][u], ah[t], bh);
                mma_bf16(acc[t][u], al[t], bh);
                mma_bf16(acc[t][u], ah[t], bl2);
            }
        }
    }
}

// pipelined GEMM mainloops
__device__ __forceinline__ void gemm_pipe_nn(char* sm, const float* A, int lda,
                                             const float* B, int ldb,
                                             int kstart, int kend, int tid,
                                             int warp, int lane, float (*acc)[4][4]) {
    float4 ra[4], rb[2];
    pfA(A, lda, kstart, tid, ra);
    pfB_nn(B, ldb, kstart, tid, rb);
    for (int k0 = kstart; k0 < kend; k0 += 32) {
        stA(sm, ra, tid);
        stB_nn(sm, rb, tid);
        __syncthreads();
        int kn = k0 + 32;
        if (kn < kend) { pfA(A, lda, kn, tid, ra); pfB_nn(B, ldb, kn, tid, rb); }
        tile_mma(sm, warp, lane, acc);
        __syncthreads();
    }
}
__device__ __forceinline__ void gemm_pipe_nt(char* sm, const float* A, int lda,
                                             const float* B, int ldb,
                                             int kstart, int kend, int tid,
                                             int warp, int lane, float (*acc)[4][4]) {
    float4 ra[4], rb[2];
    pfA(A, lda, kstart, tid, ra);
    pfB_nt(B, ldb, kstart, tid, rb);
    for (int k0 = kstart; k0 < kend; k0 += 32) {
        stA(sm, ra, tid);
        stB_nt(sm, rb, tid);
        __syncthreads();
        int kn = k0 + 32;
        if (kn < kend) { pfA(A, lda, kn, tid, ra); pfB_nt(B, ldb, kn, tid, rb); }
        tile_mma(sm, warp, lane, acc);
        __syncthreads();
    }
}

// ---------------- misc helpers ----------------
__device__ __forceinline__ void qrot(const float* q, const float* v, float* o) {
    float w=q[0], x=q[1], y=q[2], z=q[3];
    float uvx = y*v[2]-z*v[1];
    float uvy = z*v[0]-x*v[2];
    float uvz = x*v[1]-y*v[0];
    float uuvx = y*uvz-z*uvy;
    float uuvy = z*uvx-x*uvz;
    float uuvz = x*uvy-y*uvx;
    o[0]=v[0]+2.f*(w*uvx+uuvx);
    o[1]=v[1]+2.f*(w*uvy+uuvy);
    o[2]=v[2]+2.f*(w*uvz+uuvz);
}

// ---------------- setup: frames + head weights + zfuse W prep ----------------
__global__ void setup_kernel(const float* __restrict__ T, const float* __restrict__ head_weights,
                             const float* __restrict__ W_b, const float* __restrict__ W_dz) {
    int idx = blockIdx.x*256 + threadIdx.x;
    if (idx < N_) {
        int n = idx;
        const float* t = T + n*16;
        float q0=t[0], q1=t[1], q2=t[2], q3=t[3];
        float inv = rsqrtf(q0*q0+q1*q1+q2*q2+q3*q3 + 1e-8f);
        g_qn[n*4+0]=q0*inv; g_qn[n*4+1]=q1*inv; g_qn[n*4+2]=q2*inv; g_qn[n*4+3]=q3*inv;
        g_tr[n*3+0]=t[4]; g_tr[n*3+1]=t[5]; g_tr[n*3+2]=t[6];
        g_qntr[n*8+0]=q0*inv; g_qntr[n*8+1]=q1*inv; g_qntr[n*8+2]=q2*inv; g_qntr[n*8+3]=q3*inv;
        g_qntr[n*8+4]=t[4]; g_qntr[n*8+5]=t[5]; g_qntr[n*8+6]=t[6]; g_qntr[n*8+7]=0.f;
        if (n < H_) {
            float x = head_weights[n];
            float sp = (x > 20.f) ? x : log1pf(expf(x));
            g_hw[n] = sp * rsqrtf(108.0f);
        }
    } else {
        int w = idx - N_;
        if (w < 40*128) {
            int n = w >> 7, k = w & 127;
            float v = (n < 8) ? W_b[k*8 + n] : W_dz[k*32 + (n-8)];
            __nv_bfloat16 h = __float2bfloat16(v);
            g_Whz[w] = h;
            g_Wlz[w] = __float2bfloat16(v - __bfloat162float(h));
        }
    }
}

// ---------------- zfuse (R9-proven, untouched) ----------------
#define ZWST 272
__global__ void __launch_bounds__(256) zfuse_mma(const float* __restrict__ z,
                                                 const float* __restrict__ b_dz) {
    __shared__ __align__(16) char sm[2*40*ZWST];
    int tid = threadIdx.x;
    int warp = tid >> 5, lane = tid & 31;
    int gid = lane >> 2, tid4 = lane & 3;
    {
        const uint32_t* wh32 = (const uint32_t*)g_Whz;
        const uint32_t* wl32 = (const uint32_t*)g_Wlz;
        for (int i = tid; i < 40*64; i += 256) {
            int n = i >> 6, kw = i & 63;
            *(uint32_t*)(sm + n*ZWST + kw*4)           = wh32[i];
            *(uint32_t*)(sm + 40*ZWST + n*ZWST + kw*4) = wl32[i];
        }
    }
    __syncthreads();

    size_t p0 = (size_t)blockIdx.x * 256;
    const float* zb = z + (p0 + warp*32 + gid)*128;

    float acc[2][5][4] = {};
    #pragma unroll
    for (int ks = 0; ks < 8; ks++) {
        int kb = ks*16 + tid4*2;
        uint32_t ah[2][4], al[2][4];
        #pragma unroll
        for (int t = 0; t < 2; t++)
            loadA_direct(zb + (size_t)t*16*128, 128, kb, ah[t], al[t]);
        #pragma unroll
        for (int nt = 0; nt < 5; nt++) {
            int ob = (nt*8 + gid)*ZWST + kb*2;
            uint32_t bh[2], bl[2];
            bh[0] = *(const uint32_t*)(sm + ob);
            bh[1] = *(const uint32_t*)(sm + ob + 16);
            bl[0] = *(const uint32_t*)(sm + 40*ZWST + ob);
            bl[1] = *(const uint32_t*)(sm + 40*ZWST + ob + 16);
            #pragma unroll
            for (int t = 0; t < 2; t++) {
                mma_bf16(acc[t][nt], ah[t], bh);
                mma_bf16(acc[t][nt], al[t], bh);
                mma_bf16(acc[t][nt], ah[t], bl);
            }
        }
    }

    float bz[8];
    #pragma unroll
    for (int nt = 1; nt < 5; nt++) {
        int zc = nt*8 + tid4*2 - 8;
        bz[(nt-1)*2]   = b_dz[zc];
        bz[(nt-1)*2+1] = b_dz[zc+1];
    }
    #pragma unroll
    for (int t = 0; t < 2; t++) {
        size_t r0 = p0 + warp*32 + t*16 + gid;
        size_t r1 = r0 + 8;
        int c0 = tid4*2;
        g_pairb[(size_t)(c0  )*NN_ + r0] = acc[t][0][0];
        g_pairb[(size_t)(c0+1)*NN_ + r0] = acc[t][0][1];
        g_pairb[(size_t)(c0  )*NN_ + r1] = acc[t][0][2];
        g_pairb[(size_t)(c0+1)*NN_ + r1] = acc[t][0][3];
        #pragma unroll
        for (int nt = 1; nt < 5; nt++) {
            int zc = nt*8 + tid4*2 - 8;
            float bz0 = bz[(nt-1)*2], bz1 = bz[(nt-1)*2+1];
            *(float2*)(g_zdz + r0*32 + zc) = make_float2(acc[t][nt][0] + bz0, acc[t][nt][1] + bz1);
            *(float2*)(g_zdz + r1*32 + zc) = make_float2(acc[t][nt][2] + bz0, acc[t][nt][3] + bz1);
        }
    }
}

// ---------------- weight packing ----------------
__global__ void pack_kernel(const float* __restrict__ W_q, const float* __restrict__ W_kv,
                            const float* __restrict__ W_qp, const float* __restrict__ W_kp,
                            const float* __restrict__ W_vg,
                            const float* __restrict__ b_q, const float* __restrict__ b_kv,
                            const float* __restrict__ b_qp, const float* __restrict__ b_kp,
                            const float* __restrict__ b_vg) {
    int idx = blockIdx.x*256 + threadIdx.x;
    if (idx >= 384*PROJ_) return;
    int k = idx / PROJ_, c = idx % PROJ_;
    float v;
    if      (c < 1024) v = W_q [k*1024 + c];
    else if (c < 3072) v = W_kv[k*2048 + (c-1024)];
    else if (c < 3264) v = W_qp[k*192  + (c-3072)];
    else if (c < 3456) v = W_kp[k*192  + (c-3264)];
    else               v = W_vg[k*128  + (c-3456)];
    g_Wcat[idx] = v;
    if (k == 0) {
        float b;
        if      (c < 1024) b = b_q [c];
        else if (c < 3072) b = b_kv[c-1024];
        else if (c < 3264) b = b_qp[c-3072];
        else if (c < 3456) b = b_kp[c-3264];
        else               b = b_vg[c-3456];
        g_bcat[c] = b;
    }
}

// ---------------- proj: pipelined ----------------
__global__ void __launch_bounds__(256) proj_mma(const float* __restrict__ s) {
    __shared__ __align__(16) char sm[GSM];
    int tid = threadIdx.x, warp = tid >> 5, lane = tid & 31;
    int rowBase = blockIdx.y*128, nBase = blockIdx.x*64;
    float acc[2][4][4] = {};
    gemm_pipe_nn(sm, s + (size_t)rowBase*384, 384, g_Wcat + nBase, PROJ_,
                 0, 384, tid, warp, lane, acc);
    int gid = lane >> 2, tid4 = lane & 3;
    int m0 = (warp >> 1)*32, n0w = (warp & 1)*32;
    #pragma unroll
    for (int t = 0; t < 2; t++) {
        int r0 = rowBase + m0 + t*16 + gid;
        #pragma unroll
        for (int u = 0; u < 4; u++) {
            int c = nBase + n0w + u*8 + tid4*2;
            float b0 = g_bcat[c], b1 = g_bcat[c+1];
            *(float2*)(g_proj + (size_t)r0*PROJ_ + c)     = make_float2(acc[t][u][0]+b0, acc[t][u][1]+b1);
            *(float2*)(g_proj + (size_t)(r0+8)*PROJ_ + c) = make_float2(acc[t][u][2]+b0, acc[t][u][3]+b1);
        }
    }
}

// ---------------- logits: pipelined ----------------
__global__ void __launch_bounds__(256) logits_mma(const float* __restrict__ b_b,
                                                  const float* __restrict__ sw,
                                                  const float* __restrict__ mask) {
    __shared__ __align__(16) char sm[GSM];
    int tid = threadIdx.x, warp = tid >> 5, lane = tid & 31;
    int h = blockIdx.z;
    int rowBase = blockIdx.y*128, nBase = blockIdx.x*64;
    float acc[2][4][4] = {};
    gemm_pipe_nt(sm, g_Qf + ((size_t)h*N_ + rowBase)*KF_, KF_,
                 g_Kf + ((size_t)h*N_ + nBase)*KF_, KF_,
                 0, KF_, tid, warp, lane, acc);
    const float s2 = 0.57735026918962576f;
    float swh = sw[h], bbh = b_b[h];
    const float* pbh = g_pairb + (size_t)h*NN_;
    int gid = lane >> 2, tid4 = lane & 3;
    int m0 = (warp >> 1)*32, n0w = (warp & 1)*32;
    #pragma unroll
    for (int t = 0; t < 2; t++) {
        int gi0 = rowBase + m0 + t*16 + gid;
        int gi1 = gi0 + 8;
        float rc0 = g_rowc[h*N_+gi0], rc1 = g_rowc[h*N_+gi1];
        float mi0 = mask[gi0], mi1 = mask[gi1];
        #pragma unroll
        for (int u = 0; u < 4; u++) {
            int gc = nBase + n0w + u*8 + tid4*2;
            float2 pb0 = *(const float2*)(pbh + (size_t)gi0*N_ + gc);
            float2 pb1 = *(const float2*)(pbh + (size_t)gi1*N_ + gc);
            #pragma unroll
            for (int j = 0; j < 2; j++) {
                int c = gc + j;
                float cc = g_colc[h*N_+c], mj = mask[c];
                float p0 = j ? pb0.y : pb0.x;
                float p1 = j ? pb1.y : pb1.x;
                float v0 = acc[t][u][j]   + rc0 + cc + s2*(p0+bbh) + 100000.0f*(mi0*mj-1.0f);
                float v1 = acc[t][u][2+j] + rc1 + cc + s2*(p1+bbh) + 100000.0f*(mi1*mj-1.0f);
                g_A[((size_t)h*N_+gi0)*N_ + c] = v0*swh;
                g_A[((size_t)h*N_+gi1)*N_ + c] = v1*swh;
            }
        }
    }
}

// ---------------- av: pipelined ----------------
__global__ void __launch_bounds__(256) av_mma() {
    __shared__ __align__(16) char sm[GSM];
    int tid = threadIdx.x, warp = tid >> 5, lane = tid & 31;
    int h = blockIdx.z;
    int rowBase = blockIdx.y*128, nBase = blockIdx.x*64;
    float acc[2][4][4] = {};
    gemm_pipe_nn(sm, g_A + ((size_t)h*N_ + rowBase)*N_, N_,
                 g_Vcat + (size_t)h*N_*OC_ + nBase, OC_,
                 0, N_, tid, warp, lane, acc);
    int gid = lane >> 2, tid4 = lane & 3;
    int m0 = (warp >> 1)*32, n0w = (warp & 1)*32;
    #pragma unroll
    for (int t = 0; t < 2; t++) {
        int r0 = rowBase + m0 + t*16 + gid;
        #pragma unroll
        for (int u = 0; u < 4; u++) {
            int c = nBase + n0w + u*8 + tid4*2;
            *(float2*)(g_Ocat + ((size_t)h*N_ + r0)*OC_ + c)   = make_float2(acc[t][u][0], acc[t][u][1]);
            *(float2*)(g_Ocat + ((size_t)h*N_ + r0+8)*OC_ + c) = make_float2(acc[t][u][2], acc[t][u][3]);
        }
    }
}

// ---------------- wout: pipelined, split-K 6 ----------------
__global__ void __launch_bounds__(256) wout_mma(const float* __restrict__ W_out,
                                                float* __restrict__ out) {
    __shared__ __align__(16) char sm[GSM];
    int tid = threadIdx.x, warp = tid >> 5, lane = tid & 31;
    int rowBase = blockIdx.y*128, nBase = blockIdx.x*64;
    int kstart = blockIdx.z * 416;
    float acc[2][4][4] = {};
    gemm_pipe_nn(sm, g_feats + (size_t)rowBase*FEAT_, FEAT_,
                 W_out + nBase, 384,
                 kstart, kstart + 416, tid, warp, lane, acc);
    int gid = lane >> 2, tid4 = lane & 3;
    int m0 = (warp >> 1)*32, n0w = (warp & 1)*32;
    #pragma unroll
    for (int t = 0; t < 2; t++) {
        int r0 = rowBase + m0 + t*16 + gid;
        #pragma unroll
        for (int u = 0; u < 4; u++) {
            int c = nBase + n0w + u*8 + tid4*2;
            atomicAdd(&out[(size_t)r0*384 + c],       acc[t][u][0]);
            atomicAdd(&out[(size_t)r0*384 + c + 1],   acc[t][u][1]);
            atomicAdd(&out[(size_t)(r0+8)*384 + c],   acc[t][u][2]);
            atomicAdd(&out[(size_t)(r0+8)*384 + c+1], acc[t][u][3]);
        }
    }
}

// ---------------- point transforms + Qf/Kf packing ----------------
__global__ void pts_pack_kernel() {
    int n = blockIdx.x, tid = threadIdx.x;   // 128 threads
    __shared__ float sq[64*3], sk[64*3];
    __shared__ float qsq[H_], ksq[H_];
    __shared__ float qn[4], tr[3];
    if (tid<4) qn[tid]=g_qn[n*4+tid];
    if (tid>=4 && tid<7) tr[tid-4]=g_tr[n*3+tid-4];
    if (tid<H_) { qsq[tid]=0.f; ksq[tid]=0.f; }
    __syncthreads();
    if (tid < 64) {
        float p[3], o[3];
        #pragma unroll
        for (int d=0; d<3; d++) p[d]=g_proj[(size_t)n*PROJ_ + 3072 + d*64 + tid];
        qrot(qn, p, o);
        float ss=0.f;
        #pragma unroll
        for (int d=0; d<3; d++) { o[d]+=tr[d]; sq[tid*3+d]=o[d]; ss+=o[d]*o[d]; }
        atomicAdd(&qsq[tid>>3], ss);
        #pragma unroll
        for (int d=0; d<3; d++) p[d]=g_proj[(size_t)n*PROJ_ + 3264 + d*64 + tid];
        qrot(qn, p, o);
        ss=0.f;
        #pragma unroll
        for (int d=0; d<3; d++) { o[d]+=tr[d]; sk[tid*3+d]=o[d]; ss+=o[d]*o[d]; }
        atomicAdd(&ksq[tid>>3], ss);
    }
    __syncthreads();
    float s1 = rsqrtf(384.f);
    for (int t=tid; t<H_*KF_; t+=128) {
        int h=t/KF_, c=t%KF_;
        float qv, kv;
        if (c < C_) {
            qv = g_proj[(size_t)n*PROJ_ + h*C_ + c] * s1;
            kv = g_proj[(size_t)n*PROJ_ + 1024 + h*256 + c];
        } else if (c < 152) {
            int m=c-128, pp=m/3, d=m%3;
            int idx=(h*PQ_+pp)*3+d;
            qv = sq[idx]*g_hw[h];
            kv = sk[idx];
        } else { qv=0.f; kv=0.f; }
        g_Qf[((size_t)h*N_+n)*KF_ + c] = qv;
        g_Kf[((size_t)h*N_+n)*KF_ + c] = kv;
    }
    if (tid < H_) {
        g_rowc[tid*N_+n] = -0.5f*g_hw[tid]*qsq[tid];
        g_colc[tid*N_+n] = -0.5f*g_hw[tid]*ksq[tid];
    }
}

// ---------------- v_g mix + mv_transform + Vcat assembly ----------------
__global__ void vg_kernel(const float* __restrict__ gin, const float* __restrict__ W_mg) {
    int n = blockIdx.x, tid = threadIdx.x;   // 128 threads
    __shared__ float cat16[16*16];
    __shared__ float mix[64*16];
    __shared__ float qn[4], tr[3];
    if (tid<4) qn[tid]=g_qn[n*4+tid];
    if (tid>=4 && tid<7) tr[tid-4]=g_tr[n*3+tid-4];
    {
        int p=tid>>4, c=tid&15;
        cat16[p*16+c]     = g_proj[(size_t)n*PROJ_ + 3456 + p*16 + c];
        cat16[(p+8)*16+c] = gin  [(size_t)n*128 + p*16 + c];
    }
    __syncthreads();
    for (int t=tid; t<1024; t+=128) {
        int o=t>>4, c=t&15;
        float acc=0.f;
        #pragma unroll
        for (int i=0;i<16;i++) acc += W_mg[o*16+i]*cat16[i*16+c];
        mix[t]=acc;
    }
    __syncthreads();
    if (tid < 64) {
        int o=tid, h=o>>3, p=o&7;
        float mv[16];
        #pragma unroll
        for (int c=0;c<16;c++) mv[c]=mix[o*16+c];
        float out[16];
        out[0]=mv[0];
        qrot(qn, mv+1, out+1);
        qrot(qn, mv+4, out+4);
        float pv[3]; qrot(qn, mv+7, pv);
        float w=mv[10];
        out[7]=pv[0]+w*tr[0]; out[8]=pv[1]+w*tr[1]; out[9]=pv[2]+w*tr[2];
        #pragma unroll
        for (int c=10;c<16;c++) out[c]=mv[c];
        float* dst = g_Vcat + ((size_t)h*N_+n)*OC_ + 128 + p*16;
        #pragma unroll
        for (int c=0;c<16;c++) dst[c]=out[c];
    }
    for (int t=tid; t<H_*C_; t+=128) {
        int h=t>>7, c=t&127;
        g_Vcat[((size_t)h*N_+n)*OC_ + c] = g_proj[(size_t)n*PROJ_ + 1024 + h*256 + 128 + c];
    }
}

// ---------------- row softmax + fused o_rel accumulation ----------------
__global__ void __launch_bounds__(256) softmax_kernel() {
    __shared__ float qt[512*9];
    int tid = threadIdx.x;
    int warp = tid >> 5, lane = tid & 31;
    for (int t = tid; t < 512; t += 256) {
        #pragma unroll
        for (int c=0;c<8;c++) qt[t*9+c] = g_qntr[t*8+c];
    }
    __syncthreads();
    int row = blockIdx.x*8 + warp;
    float* a = g_A + (size_t)row*N_;
    float v[16];
    #pragma unroll
    for (int t=0;t<16;t++) v[t] = a[lane + 32*t];
    float m = v[0];
    #pragma unroll
    for (int t=1;t<16;t++) m = fmaxf(m, v[t]);
    #pragma unroll
    for (int off=16; off>0; off>>=1) m = fmaxf(m, __shfl_xor_sync(0xffffffff, m, off));
    float s = 0.f;
    #pragma unroll
    for (int t=0;t<16;t++) { v[t] = expf(v[t]-m); s += v[t]; }
    #pragma unroll
    for (int off=16; off>0; off>>=1) s += __shfl_xor_sync(0xffffffff, s, off);
    float inv = 1.f/s;
    float orel[8] = {};
    #pragma unroll
    for (int t=0;t<16;t++) {
        float p = v[t]*inv;
        a[lane + 32*t] = p;
        const float* q = qt + (lane + 32*t)*9;
        #pragma unroll
        for (int c=0;c<8;c++) orel[c] += p*q[c];
    }
    #pragma unroll
    for (int c=0;c<8;c++) {
        #pragma unroll
        for (int off=16; off>0; off>>=1)
            orel[c] += __shfl_xor_sync(0xffffffff, orel[c], off);
    }
    if (lane == 0) {
        #pragma unroll
        for (int c=0;c<8;c++) g_Orel[(size_t)row*8+c] = orel[c];
    }
}

// ---------------- o_pair (R9 staged) ----------------
__global__ void opair_kernel() {
    int i = blockIdx.x;
    int tid = threadIdx.x;  // 256
    __shared__ float Zs[64*33];
    __shared__ float Asm[8*64];
    int hh = tid>>5, cc = tid&31;
    float acc = 0.f;
    for (int jt=0; jt<N_; jt+=64) {
        __syncthreads();
        for (int t=tid; t<2048; t+=256) {
            int jj=t>>5, c=t&31;
            Zs[jj*33+c] = g_zdz[((size_t)i*N_ + jt+jj)*32 + c];
        }
        for (int t=tid; t<512; t+=256) {
            int h=t>>6, jj=t&63;
            Asm[h*64+jj] = g_A[((size_t)h*N_+i)*N_ + jt+jj];
        }
        __syncthreads();
        #pragma unroll
        for (int jj=0; jj<64; jj++) acc += Asm[hh*64+jj]*Zs[jj*33+cc];
    }
    g_feats[(size_t)i*FEAT_ + hh*SEG_ + cc] = acc;
}

// ---------------- finalize ----------------
__global__ void finalize_kernel() {
    int n = blockIdx.x, tid = threadIdx.x;  // 128
    __shared__ float qn[4], tr[3];
    if (tid<4) qn[tid]=g_qn[n*4+tid];
    if (tid>=4 && tid<7) tr[tid-4]=g_tr[n*3+tid-4];
    __syncthreads();
    for (int t=tid; t<H_*C_; t+=128) {
        int h=t>>7, c=t&127;
        g_feats[(size_t)n*FEAT_ + h*SEG_ + 32 + c] = g_Ocat[((size_t)h*N_+n)*OC_ + c];
    }
    if (tid < 64) {
        int h=tid>>3, p=tid&7;
        const float* oc = g_Ocat + ((size_t)h*N_+n)*OC_ + 128 + p*16;
        float mv[16];
        #pragma unroll
        for (int c=0;c<16;c++) mv[c]=oc[c];
        float qc[4] = {qn[0], -qn[1], -qn[2], -qn[3]};
        float out[16];
        out[0]=mv[0];
        qrot(qc, mv+1, out+1);
        qrot(qc, mv+4, out+4);
        float w=mv[10];
        float tmp[3] = {mv[7]-w*tr[0], mv[8]-w*tr[1], mv[9]-w*tr[2]};
        qrot(qc, tmp, out+7);
        #pragma unroll
        for (int c=10;c<16;c++) out[c]=mv[c];
        float s1v=1e-8f, s2v=1e-8f;
        #pragma unroll
        for (int c=0;c<10;c++) s1v += out[c]*out[c];
        #pragma unroll
        for (int c=10;c<16;c++) s2v += out[c]*out[c];
        float* f = g_feats + (size_t)n*FEAT_ + h*SEG_;
        #pragma unroll
        for (int c=0;c<16;c++) f[168+p*16+c]=out[c];
        f[296+p*2+0]=sqrtf(s1v);
        f[296+p*2+1]=sqrtf(s2v);
    }
    if (tid < H_) {
        int h=tid;
        const float* oc = g_Orel + ((size_t)h*N_+n)*8;
        float aq0=oc[0], aq1=oc[1], aq2=oc[2], aq3=oc[3];
        float qc[4] = {qn[0], -qn[1], -qn[2], -qn[3]};
        float qr0 = qc[0]*aq0 - qc[1]*aq1 - qc[2]*aq2 - qc[3]*aq3;
        float qr1 = qc[0]*aq1 + qc[1]*aq0 + qc[2]*aq3 - qc[3]*aq2;
        float qr2 = qc[0]*aq2 - qc[1]*aq3 + qc[2]*aq0 + qc[3]*aq1;
        float qr3 = qc[0]*aq3 + qc[1]*aq2 - qc[2]*aq1 + qc[3]*aq0;
        float d[3] = {oc[4]-tr[0], oc[5]-tr[1], oc[6]-tr[2]};
        float trel[3];
        qrot(qc, d, trel);
        float* f = g_feats + (size_t)n*FEAT_ + h*SEG_ + 160;
        f[0]=qr0; f[1]=qr1; f[2]=qr2; f[3]=qr3;
        f[4]=trel[0]; f[5]=trel[1]; f[6]=trel[2]; f[7]=0.f;
    }
}

// ---------------- out init (bias) ----------------
__global__ void out_init_kernel(float* __restrict__ out, const float* __restrict__ b_out) {
    int idx = blockIdx.x*256 + threadIdx.x;
    if (idx < 512*384) out[idx] = b_out[idx % 384];
}

// ---------------- g_out ----------------
__global__ void gout_kernel(const float* __restrict__ W_geo, float* __restrict__ out) {
    int n = blockIdx.x, tid = threadIdx.x;  // 128
    int o = tid>>4, c = tid&15;
    float acc = 0.f;
    #pragma unroll
    for (int i2=0; i2<64; i2++) {
        acc += W_geo[o*64+i2] * g_feats[(size_t)n*FEAT_ + (i2>>3)*SEG_ + 168 + (i2&7)*16 + c];
    }
    out[(size_t)n*128 + o*16 + c] = acc;
}

// ---------------- launch ----------------
extern "C" void kernel_launch(void* const* d_in, const int* in_sizes, int n_in,
                              void* d_out, int out_size) {
    const float* s    = (const float*)d_in[0];
    const float* gin  = (const float*)d_in[1];
    const float* z    = (const float*)d_in[2];
    const float* T    = (const float*)d_in[3];
    const float* mask = (const float*)d_in[4];
    const float* W_q  = (const float*)d_in[5];
    const float* b_q  = (const float*)d_in[6];
    const float* W_kv = (const float*)d_in[7];
    const float* b_kv = (const float*)d_in[8];
    const float* W_qp = (const float*)d_in[9];
    const float* b_qp = (const float*)d_in[10];
    const float* W_kp = (const float*)d_in[11];
    const float* b_kp = (const float*)d_in[12];
    const float* W_vg = (const float*)d_in[13];
    const float* b_vg = (const float*)d_in[14];
    const float* W_mg = (const float*)d_in[15];
    const float* W_b  = (const float*)d_in[16];
    const float* b_b  = (const float*)d_in[17];
    const float* W_dz = (const float*)d_in[18];
    const float* b_dz = (const float*)d_in[19];
    const float* head_weights    = (const float*)d_in[20];
    const float* softmax_weights = (const float*)d_in[21];
    const float* W_out = (const float*)d_in[22];
    const float* b_out = (const float*)d_in[23];
    const float* W_geo = (const float*)d_in[24];
    float* out = (float*)d_out;

    setup_kernel<<<(N_ + 40*128 + 255)/256, 256>>>(T, head_weights, W_b, W_dz);
    pack_kernel<<<(384*PROJ_+255)/256,256>>>(W_q,W_kv,W_qp,W_kp,W_vg, b_q,b_kv,b_qp,b_kp,b_vg);
    zfuse_mma<<<1024,256>>>(z, b_dz);

    proj_mma<<<dim3(PROJ_/64, 4), 256>>>(s);

    pts_pack_kernel<<<512,128>>>();
    vg_kernel<<<512,128>>>(gin, W_mg);

    logits_mma<<<dim3(8,4,8), 256>>>(b_b, softmax_weights, mask);
    softmax_kernel<<<512,256>>>();
    av_mma<<<dim3(4,4,8), 256>>>();
    opair_kernel<<<512,256>>>();
    finalize_kernel<<<512,128>>>();

    out_init_kernel<<<768,256>>>(out, b_out);
    wout_mma<<<dim3(6,4,6), 256>>>(W_out, out);
    gout_kernel<<<512,128>>>(W_geo, out + 512*384);
}

// round 17
// speedup vs baseline: 1.6456x; 1.0212x over previous
#include <cuda_runtime.h>
#include <cuda_bf16.h>
#include <math.h>
#include <stdint.h>

#define N_    512
#define H_    8
#define C_    128
#define PQ_   8
#define PV_   8
#define KF_   160
#define OC_   256
#define SEG_  312
#define FEAT_ 2496
#define PROJ_ 3584
#define NN_   ((size_t)N_*N_)

// ---------------- scratch ----------------
static __device__ float g_Wcat[384*PROJ_];
static __device__ float g_bcat[PROJ_];
static __device__ float g_proj[(size_t)N_*PROJ_];
static __device__ float g_Qf[(size_t)H_*N_*KF_];
static __device__ float g_Kf[(size_t)H_*N_*KF_];
static __device__ float g_rowc[H_*N_];
static __device__ float g_colc[H_*N_];
static __device__ float g_qn[N_*4];
static __device__ float g_tr[N_*3];
static __device__ float g_qntr[N_*8];
static __device__ float g_hw[H_];
static __device__ float g_pairb[(size_t)H_*NN_];   // [h][i][j]
static __device__ float g_zdz[(size_t)NN_*32];
static __device__ float g_A[(size_t)H_*N_*N_];
static __device__ float g_Vcat[(size_t)H_*N_*OC_];
static __device__ float g_Ocat[(size_t)H_*N_*OC_];
static __device__ float g_Orel[(size_t)H_*N_*8];
static __device__ float g_feats[(size_t)N_*FEAT_];
static __device__ __nv_bfloat16 g_Whz[40*128];
static __device__ __nv_bfloat16 g_Wlz[40*128];

// ---------------- mma helpers ----------------
__device__ __forceinline__ void mma_bf16(float* d, const uint32_t* a, const uint32_t* b) {
    asm volatile(
        "mma.sync.aligned.m16n8k16.row.col.f32.bf16.bf16.f32 "
        "{%0,%1,%2,%3}, {%4,%5,%6,%7}, {%8,%9}, {%0,%1,%2,%3};"
        : "+f"(d[0]), "+f"(d[1]), "+f"(d[2]), "+f"(d[3])
        : "r"(a[0]), "r"(a[1]), "r"(a[2]), "r"(a[3]), "r"(b[0]), "r"(b[1]));
}
__device__ __forceinline__ uint32_t packbf2(float x, float y) {
    __nv_bfloat16 hx = __float2bfloat16(x), hy = __float2bfloat16(y);
    return (uint32_t)__bfloat16_as_ushort(hx) | ((uint32_t)__bfloat16_as_ushort(hy) << 16);
}
__device__ __forceinline__ uint32_t packlo2(float x, float y) {
    float rx = x - __bfloat162float(__float2bfloat16(x));
    float ry = y - __bfloat162float(__float2bfloat16(y));
    return packbf2(rx, ry);
}
__device__ __forceinline__ void splitf(float v, uint16_t& h, uint16_t& l) {
    __nv_bfloat16 hb = __float2bfloat16(v);
    h = __bfloat16_as_ushort(hb);
    l = __bfloat16_as_ushort(__float2bfloat16(v - __bfloat162float(hb)));
}
__device__ __forceinline__ void loadA_direct(const float* Abase, int lda, int kb,
                                             uint32_t* ah, uint32_t* al) {
    float2 v0 = *(const float2*)(Abase + kb);
    float2 v1 = *(const float2*)(Abase + (size_t)8*lda + kb);
    float2 v2 = *(const float2*)(Abase + kb + 8);
    float2 v3 = *(const float2*)(Abase + (size_t)8*lda + kb + 8);
    ah[0] = packbf2(v0.x, v0.y);  al[0] = packlo2(v0.x, v0.y);
    ah[1] = packbf2(v1.x, v1.y);  al[1] = packlo2(v1.x, v1.y);
    ah[2] = packbf2(v2.x, v2.y);  al[2] = packlo2(v2.x, v2.y);
    ah[3] = packbf2(v3.x, v3.y);  al[3] = packlo2(v3.x, v3.y);
}

// shared-tile GEMM geometry (R9-proven), double-buffered
#define AST 40
#define BST 40
#define AH_OFF 0
#define AL_OFF 10240
#define BH_OFF 20480
#define BL_OFF 25600
#define GSM    30720

// ---- register prefetch / store (software pipeline) ----
__device__ __forceinline__ void pfA(const float* A, int lda, int k0, int tid, float4* ra) {
    #pragma unroll
    for (int j = 0; j < 4; j++) {
        int i = tid*4 + j*1024;
        ra[j] = *(const float4*)(A + (size_t)(i>>5)*lda + k0 + (i&31));
    }
}
__device__ __forceinline__ void stA(char* sm, const float4* ra, int tid) {
    #pragma unroll
    for (int j = 0; j < 4; j++) {
        int i = tid*4 + j*1024;
        int r = i>>5, k = i&31;
        float4 v = ra[j];
        char* ph = sm + AH_OFF + (r*AST + k)*2;
        *(uint32_t*)(ph)   = packbf2(v.x, v.y);
        *(uint32_t*)(ph+4) = packbf2(v.z, v.w);
        char* pl = sm + AL_OFF + (r*AST + k)*2;
        *(uint32_t*)(pl)   = packlo2(v.x, v.y);
        *(uint32_t*)(pl+4) = packlo2(v.z, v.w);
    }
}
__device__ __forceinline__ void pfB_nn(const float* B, int ldb, int k0, int tid, float4* rb) {
    #pragma unroll
    for (int j = 0; j < 2; j++) {
        int i = tid*4 + j*1024;
        int k = i>>6, n = i&63;
        rb[j] = *(const float4*)(B + (size_t)(k0+k)*ldb + n);
    }
}
__device__ __forceinline__ void stB_nn(char* sm, const float4* rb, int tid) {
    #pragma unroll
    for (int j = 0; j < 2; j++) {
        int i = tid*4 + j*1024;
        int k = i>>6, n = i&63;
        float vv[4] = {rb[j].x, rb[j].y, rb[j].z, rb[j].w};
        #pragma unroll
        for (int jj = 0; jj < 4; jj++) {
            uint16_t h, l; splitf(vv[jj], h, l);
            *(uint16_t*)(sm + BH_OFF + ((n+jj)*BST + k)*2) = h;
            *(uint16_t*)(sm + BL_OFF + ((n+jj)*BST + k)*2) = l;
        }
    }
}
__device__ __forceinline__ void pfB_nt(const float* B, int ldb, int k0, int tid, float4* rb) {
    #pragma unroll
    for (int j = 0; j < 2; j++) {
        int i = tid*4 + j*1024;
        int n = i>>5, k = i&31;
        rb[j] = *(const float4*)(B + (size_t)n*ldb + k0 + k);
    }
}
__device__ __forceinline__ void stB_nt(char* sm, const float4* rb, int tid) {
    #pragma unroll
    for (int j = 0; j < 2; j++) {
        int i = tid*4 + j*1024;
        int n = i>>5, k = i&31;
        float4 v = rb[j];
        char* ph = sm + BH_OFF + (n*BST + k)*2;
        *(uint32_t*)(ph)   = packbf2(v.x, v.y);
        *(uint32_t*)(ph+4) = packbf2(v.z, v.w);
        char* pl = sm + BL_OFF + (n*BST + k)*2;
        *(uint32_t*)(pl)   = packlo2(v.x, v.y);
        *(uint32_t*)(pl+4) = packlo2(v.z, v.w);
    }
}
__device__ __forceinline__ void tile_mma(const char* sm, int warp, int lane, float (*acc)[4][4]) {
    int gid = lane >> 2, tid4 = lane & 3;
    int m0 = (warp >> 1)*32, n0 = (warp & 1)*32;
    #pragma unroll
    for (int ks = 0; ks < 2; ks++) {
        int kb = ks*16 + tid4*2;
        uint32_t ah[2][4], al[2][4];
        #pragma unroll
        for (int t = 0; t < 2; t++) {
            const char* ba = sm + AH_OFF + ((m0 + t*16 + gid)*AST + kb)*2;
            ah[t][0] = *(const uint32_t*)(ba);
            ah[t][1] = *(const uint32_t*)(ba + 8*AST*2);
            ah[t][2] = *(const uint32_t*)(ba + 16);
            ah[t][3] = *(const uint32_t*)(ba + 8*AST*2 + 16);
            const char* bal = ba + (AL_OFF - AH_OFF);
            al[t][0] = *(const uint32_t*)(bal);
            al[t][1] = *(const uint32_t*)(bal + 8*AST*2);
            al[t][2] = *(const uint32_t*)(bal + 16);
            al[t][3] = *(const uint32_t*)(bal + 8*AST*2 + 16);
        }
        #pragma unroll
        for (int u = 0; u < 4; u++) {
            const char* bb = sm + BH_OFF + ((n0 + u*8 + gid)*BST + kb)*2;
            uint32_t bh[2] = { *(const uint32_t*)bb, *(const uint32_t*)(bb+16) };
            const char* bbl = bb + (BL_OFF - BH_OFF);
            uint32_t bl2[2] = { *(const uint32_t*)bbl, *(const uint32_t*)(bbl+16) };
            #pragma unroll
            for (int t = 0; t < 2; t++) {
                mma_bf16(acc[t][u], ah[t], bh);
                mma_bf16(acc[t][u], al[t], bh);
                mma_bf16(acc[t][u], ah[t], bl2);
            }
        }
    }
}

// double-buffered pipelined GEMM mainloops (one barrier per chunk)
__device__ __forceinline__ void gemm_pipe_nn(char* sm, const float* A, int lda,
                                             const float* B, int ldb,
                                             int kstart, int kend, int tid,
                                             int warp, int lane, float (*acc)[4][4]) {
    float4 ra[4], rb[2];
    pfA(A, lda, kstart, tid, ra);
    pfB_nn(B, ldb, kstart, tid, rb);
    int buf = 0;
    for (int k0 = kstart; k0 < kend; k0 += 32) {
        char* smb = sm + buf*GSM;
        stA(smb, ra, tid);
        stB_nn(smb, rb, tid);
        __syncthreads();
        int kn = k0 + 32;
        if (kn < kend) { pfA(A, lda, kn, tid, ra); pfB_nn(B, ldb, kn, tid, rb); }
        tile_mma(smb, warp, lane, acc);
        buf ^= 1;
    }
}
__device__ __forceinline__ void gemm_pipe_nt(char* sm, const float* A, int lda,
                                             const float* B, int ldb,
                                             int kstart, int kend, int tid,
                                             int warp, int lane, float (*acc)[4][4]) {
    float4 ra[4], rb[2];
    pfA(A, lda, kstart, tid, ra);
    pfB_nt(B, ldb, kstart, tid, rb);
    int buf = 0;
    for (int k0 = kstart; k0 < kend; k0 += 32) {
        char* smb = sm + buf*GSM;
        stA(smb, ra, tid);
        stB_nt(smb, rb, tid);
        __syncthreads();
        int kn = k0 + 32;
        if (kn < kend) { pfA(A, lda, kn, tid, ra); pfB_nt(B, ldb, kn, tid, rb); }
        tile_mma(smb, warp, lane, acc);
        buf ^= 1;
    }
}

// ---------------- misc helpers ----------------
__device__ __forceinline__ void qrot(const float* q, const float* v, float* o) {
    float w=q[0], x=q[1], y=q[2], z=q[3];
    float uvx = y*v[2]-z*v[1];
    float uvy = z*v[0]-x*v[2];
    float uvz = x*v[1]-y*v[0];
    float uuvx = y*uvz-z*uvy;
    float uuvy = z*uvx-x*uvz;
    float uuvz = x*uvy-y*uvx;
    o[0]=v[0]+2.f*(w*uvx+uuvx);
    o[1]=v[1]+2.f*(w*uvy+uuvy);
    o[2]=v[2]+2.f*(w*uvz+uuvz);
}

// ---------------- setup: frames + head weights + zfuse W prep ----------------
__global__ void setup_kernel(const float* __restrict__ T, const float* __restrict__ head_weights,
                             const float* __restrict__ W_b, const float* __restrict__ W_dz) {
    int idx = blockIdx.x*256 + threadIdx.x;
    if (idx < N_) {
        int n = idx;
        const float* t = T + n*16;
        float q0=t[0], q1=t[1], q2=t[2], q3=t[3];
        float inv = rsqrtf(q0*q0+q1*q1+q2*q2+q3*q3 + 1e-8f);
        g_qn[n*4+0]=q0*inv; g_qn[n*4+1]=q1*inv; g_qn[n*4+2]=q2*inv; g_qn[n*4+3]=q3*inv;
        g_tr[n*3+0]=t[4]; g_tr[n*3+1]=t[5]; g_tr[n*3+2]=t[6];
        g_qntr[n*8+0]=q0*inv; g_qntr[n*8+1]=q1*inv; g_qntr[n*8+2]=q2*inv; g_qntr[n*8+3]=q3*inv;
        g_qntr[n*8+4]=t[4]; g_qntr[n*8+5]=t[5]; g_qntr[n*8+6]=t[6]; g_qntr[n*8+7]=0.f;
        if (n < H_) {
            float x = head_weights[n];
            float sp = (x > 20.f) ? x : log1pf(expf(x));
            g_hw[n] = sp * rsqrtf(108.0f);
        }
    } else {
        int w = idx - N_;
        if (w < 40*128) {
            int n = w >> 7, k = w & 127;
            float v = (n < 8) ? W_b[k*8 + n] : W_dz[k*32 + (n-8)];
            __nv_bfloat16 h = __float2bfloat16(v);
            g_Whz[w] = h;
            g_Wlz[w] = __float2bfloat16(v - __bfloat162float(h));
        }
    }
}

// ---------------- zfuse (R9-proven, untouched) ----------------
#define ZWST 272
__global__ void __launch_bounds__(256) zfuse_mma(const float* __restrict__ z,
                                                 const float* __restrict__ b_dz) {
    __shared__ __align__(16) char sm[2*40*ZWST];
    int tid = threadIdx.x;
    int warp = tid >> 5, lane = tid & 31;
    int gid = lane >> 2, tid4 = lane & 3;
    {
        const uint32_t* wh32 = (const uint32_t*)g_Whz;
        const uint32_t* wl32 = (const uint32_t*)g_Wlz;
        for (int i = tid; i < 40*64; i += 256) {
            int n = i >> 6, kw = i & 63;
            *(uint32_t*)(sm + n*ZWST + kw*4)           = wh32[i];
            *(uint32_t*)(sm + 40*ZWST + n*ZWST + kw*4) = wl32[i];
        }
    }
    __syncthreads();

    size_t p0 = (size_t)blockIdx.x * 256;
    const float* zb = z + (p0 + warp*32 + gid)*128;

    float acc[2][5][4] = {};
    #pragma unroll
    for (int ks = 0; ks < 8; ks++) {
        int kb = ks*16 + tid4*2;
        uint32_t ah[2][4], al[2][4];
        #pragma unroll
        for (int t = 0; t < 2; t++)
            loadA_direct(zb + (size_t)t*16*128, 128, kb, ah[t], al[t]);
        #pragma unroll
        for (int nt = 0; nt < 5; nt++) {
            int ob = (nt*8 + gid)*ZWST + kb*2;
            uint32_t bh[2], bl[2];
            bh[0] = *(const uint32_t*)(sm + ob);
            bh[1] = *(const uint32_t*)(sm + ob + 16);
            bl[0] = *(const uint32_t*)(sm + 40*ZWST + ob);
            bl[1] = *(const uint32_t*)(sm + 40*ZWST + ob + 16);
            #pragma unroll
            for (int t = 0; t < 2; t++) {
                mma_bf16(acc[t][nt], ah[t], bh);
                mma_bf16(acc[t][nt], al[t], bh);
                mma_bf16(acc[t][nt], ah[t], bl);
            }
        }
    }

    float bz[8];
    #pragma unroll
    for (int nt = 1; nt < 5; nt++) {
        int zc = nt*8 + tid4*2 - 8;
        bz[(nt-1)*2]   = b_dz[zc];
        bz[(nt-1)*2+1] = b_dz[zc+1];
    }
    #pragma unroll
    for (int t = 0; t < 2; t++) {
        size_t r0 = p0 + warp*32 + t*16 + gid;
        size_t r1 = r0 + 8;
        int c0 = tid4*2;
        g_pairb[(size_t)(c0  )*NN_ + r0] = acc[t][0][0];
        g_pairb[(size_t)(c0+1)*NN_ + r0] = acc[t][0][1];
        g_pairb[(size_t)(c0  )*NN_ + r1] = acc[t][0][2];
        g_pairb[(size_t)(c0+1)*NN_ + r1] = acc[t][0][3];
        #pragma unroll
        for (int nt = 1; nt < 5; nt++) {
            int zc = nt*8 + tid4*2 - 8;
            float bz0 = bz[(nt-1)*2], bz1 = bz[(nt-1)*2+1];
            *(float2*)(g_zdz + r0*32 + zc) = make_float2(acc[t][nt][0] + bz0, acc[t][nt][1] + bz1);
            *(float2*)(g_zdz + r1*32 + zc) = make_float2(acc[t][nt][2] + bz0, acc[t][nt][3] + bz1);
        }
    }
}

// ---------------- weight packing ----------------
__global__ void pack_kernel(const float* __restrict__ W_q, const float* __restrict__ W_kv,
                            const float* __restrict__ W_qp, const float* __restrict__ W_kp,
                            const float* __restrict__ W_vg,
                            const float* __restrict__ b_q, const float* __restrict__ b_kv,
                            const float* __restrict__ b_qp, const float* __restrict__ b_kp,
                            const float* __restrict__ b_vg) {
    int idx = blockIdx.x*256 + threadIdx.x;
    if (idx >= 384*PROJ_) return;
    int k = idx / PROJ_, c = idx % PROJ_;
    float v;
    if      (c < 1024) v = W_q [k*1024 + c];
    else if (c < 3072) v = W_kv[k*2048 + (c-1024)];
    else if (c < 3264) v = W_qp[k*192  + (c-3072)];
    else if (c < 3456) v = W_kp[k*192  + (c-3264)];
    else               v = W_vg[k*128  + (c-3456)];
    g_Wcat[idx] = v;
    if (k == 0) {
        float b;
        if      (c < 1024) b = b_q [c];
        else if (c < 3072) b = b_kv[c-1024];
        else if (c < 3264) b = b_qp[c-3072];
        else if (c < 3456) b = b_kp[c-3264];
        else               b = b_vg[c-3456];
        g_bcat[c] = b;
    }
}

// ---------------- proj: pipelined, double-buffered ----------------
__global__ void __launch_bounds__(256) proj_mma(const float* __restrict__ s) {
    __shared__ __align__(16) char sm[2*GSM];
    int tid = threadIdx.x, warp = tid >> 5, lane = tid & 31;
    int rowBase = blockIdx.y*128, nBase = blockIdx.x*64;
    float acc[2][4][4] = {};
    gemm_pipe_nn(sm, s + (size_t)rowBase*384, 384, g_Wcat + nBase, PROJ_,
                 0, 384, tid, warp, lane, acc);
    int gid = lane >> 2, tid4 = lane & 3;
    int m0 = (warp >> 1)*32, n0w = (warp & 1)*32;
    #pragma unroll
    for (int t = 0; t < 2; t++) {
        int r0 = rowBase + m0 + t*16 + gid;
        #pragma unroll
        for (int u = 0; u < 4; u++) {
            int c = nBase + n0w + u*8 + tid4*2;
            float b0 = g_bcat[c], b1 = g_bcat[c+1];
            *(float2*)(g_proj + (size_t)r0*PROJ_ + c)     = make_float2(acc[t][u][0]+b0, acc[t][u][1]+b1);
            *(float2*)(g_proj + (size_t)(r0+8)*PROJ_ + c) = make_float2(acc[t][u][2]+b0, acc[t][u][3]+b1);
        }
    }
}

// ---------------- logits: pipelined, double-buffered ----------------
__global__ void __launch_bounds__(256) logits_mma(const float* __restrict__ b_b,
                                                  const float* __restrict__ sw,
                                                  const float* __restrict__ mask) {
    __shared__ __align__(16) char sm[2*GSM];
    int tid = threadIdx.x, warp = tid >> 5, lane = tid & 31;
    int h = blockIdx.z;
    int rowBase = blockIdx.y*128, nBase = blockIdx.x*64;
    float acc[2][4][4] = {};
    gemm_pipe_nt(sm, g_Qf + ((size_t)h*N_ + rowBase)*KF_, KF_,
                 g_Kf + ((size_t)h*N_ + nBase)*KF_, KF_,
                 0, KF_, tid, warp, lane, acc);
    const float s2 = 0.57735026918962576f;
    float swh = sw[h], bbh = b_b[h];
    const float* pbh = g_pairb + (size_t)h*NN_;
    int gid = lane >> 2, tid4 = lane & 3;
    int m0 = (warp >> 1)*32, n0w = (warp & 1)*32;
    #pragma unroll
    for (int t = 0; t < 2; t++) {
        int gi0 = rowBase + m0 + t*16 + gid;
        int gi1 = gi0 + 8;
        float rc0 = g_rowc[h*N_+gi0], rc1 = g_rowc[h*N_+gi1];
        float mi0 = mask[gi0], mi1 = mask[gi1];
        #pragma unroll
        for (int u = 0; u < 4; u++) {
            int gc = nBase + n0w + u*8 + tid4*2;
            float2 pb0 = *(const float2*)(pbh + (size_t)gi0*N_ + gc);
            float2 pb1 = *(const float2*)(pbh + (size_t)gi1*N_ + gc);
            #pragma unroll
            for (int j = 0; j < 2; j++) {
                int c = gc + j;
                float cc = g_colc[h*N_+c], mj = mask[c];
                float p0 = j ? pb0.y : pb0.x;
                float p1 = j ? pb1.y : pb1.x;
                float v0 = acc[t][u][j]   + rc0 + cc + s2*(p0+bbh) + 100000.0f*(mi0*mj-1.0f);
                float v1 = acc[t][u][2+j] + rc1 + cc + s2*(p1+bbh) + 100000.0f*(mi1*mj-1.0f);
                g_A[((size_t)h*N_+gi0)*N_ + c] = v0*swh;
                g_A[((size_t)h*N_+gi1)*N_ + c] = v1*swh;
            }
        }
    }
}

// ---------------- av: pipelined, double-buffered ----------------
__global__ void __launch_bounds__(256) av_mma() {
    __shared__ __align__(16) char sm[2*GSM];
    int tid = threadIdx.x, warp = tid >> 5, lane = tid & 31;
    int h = blockIdx.z;
    int rowBase = blockIdx.y*128, nBase = blockIdx.x*64;
    float acc[2][4][4] = {};
    gemm_pipe_nn(sm, g_A + ((size_t)h*N_ + rowBase)*N_, N_,
                 g_Vcat + (size_t)h*N_*OC_ + nBase, OC_,
                 0, N_, tid, warp, lane, acc);
    int gid = lane >> 2, tid4 = lane & 3;
    int m0 = (warp >> 1)*32, n0w = (warp & 1)*32;
    #pragma unroll
    for (int t = 0; t < 2; t++) {
        int r0 = rowBase + m0 + t*16 + gid;
        #pragma unroll
        for (int u = 0; u < 4; u++) {
            int c = nBase + n0w + u*8 + tid4*2;
            *(float2*)(g_Ocat + ((size_t)h*N_ + r0)*OC_ + c)   = make_float2(acc[t][u][0], acc[t][u][1]);
            *(float2*)(g_Ocat + ((size_t)h*N_ + r0+8)*OC_ + c) = make_float2(acc[t][u][2], acc[t][u][3]);
        }
    }
}

// ---------------- wout: pipelined, double-buffered, split-K 6 ----------------
__global__ void __launch_bounds__(256) wout_mma(const float* __restrict__ W_out,
                                                float* __restrict__ out) {
    __shared__ __align__(16) char sm[2*GSM];
    int tid = threadIdx.x, warp = tid >> 5, lane = tid & 31;
    int rowBase = blockIdx.y*128, nBase = blockIdx.x*64;
    int kstart = blockIdx.z * 416;
    float acc[2][4][4] = {};
    gemm_pipe_nn(sm, g_feats + (size_t)rowBase*FEAT_, FEAT_,
                 W_out + nBase, 384,
                 kstart, kstart + 416, tid, warp, lane, acc);
    int gid = lane >> 2, tid4 = lane & 3;
    int m0 = (warp >> 1)*32, n0w = (warp & 1)*32;
    #pragma unroll
    for (int t = 0; t < 2; t++) {
        int r0 = rowBase + m0 + t*16 + gid;
        #pragma unroll
        for (int u = 0; u < 4; u++) {
            int c = nBase + n0w + u*8 + tid4*2;
            atomicAdd(&out[(size_t)r0*384 + c],       acc[t][u][0]);
            atomicAdd(&out[(size_t)r0*384 + c + 1],   acc[t][u][1]);
            atomicAdd(&out[(size_t)(r0+8)*384 + c],   acc[t][u][2]);
            atomicAdd(&out[(size_t)(r0+8)*384 + c+1], acc[t][u][3]);
        }
    }
}

// ---------------- point transforms + Qf/Kf packing ----------------
__global__ void pts_pack_kernel() {
    int n = blockIdx.x, tid = threadIdx.x;   // 128 threads
    __shared__ float sq[64*3], sk[64*3];
    __shared__ float qsq[H_], ksq[H_];
    __shared__ float qn[4], tr[3];
    if (tid<4) qn[tid]=g_qn[n*4+tid];
    if (tid>=4 && tid<7) tr[tid-4]=g_tr[n*3+tid-4];
    if (tid<H_) { qsq[tid]=0.f; ksq[tid]=0.f; }
    __syncthreads();
    if (tid < 64) {
        float p[3], o[3];
        #pragma unroll
        for (int d=0; d<3; d++) p[d]=g_proj[(size_t)n*PROJ_ + 3072 + d*64 + tid];
        qrot(qn, p, o);
        float ss=0.f;
        #pragma unroll
        for (int d=0; d<3; d++) { o[d]+=tr[d]; sq[tid*3+d]=o[d]; ss+=o[d]*o[d]; }
        atomicAdd(&qsq[tid>>3], ss);
        #pragma unroll
        for (int d=0; d<3; d++) p[d]=g_proj[(size_t)n*PROJ_ + 3264 + d*64 + tid];
        qrot(qn, p, o);
        ss=0.f;
        #pragma unroll
        for (int d=0; d<3; d++) { o[d]+=tr[d]; sk[tid*3+d]=o[d]; ss+=o[d]*o[d]; }
        atomicAdd(&ksq[tid>>3], ss);
    }
    __syncthreads();
    float s1 = rsqrtf(384.f);
    for (int t=tid; t<H_*KF_; t+=128) {
        int h=t/KF_, c=t%KF_;
        float qv, kv;
        if (c < C_) {
            qv = g_proj[(size_t)n*PROJ_ + h*C_ + c] * s1;
            kv = g_proj[(size_t)n*PROJ_ + 1024 + h*256 + c];
        } else if (c < 152) {
            int m=c-128, pp=m/3, d=m%3;
            int idx=(h*PQ_+pp)*3+d;
            qv = sq[idx]*g_hw[h];
            kv = sk[idx];
        } else { qv=0.f; kv=0.f; }
        g_Qf[((size_t)h*N_+n)*KF_ + c] = qv;
        g_Kf[((size_t)h*N_+n)*KF_ + c] = kv;
    }
    if (tid < H_) {
        g_rowc[tid*N_+n] = -0.5f*g_hw[tid]*qsq[tid];
        g_colc[tid*N_+n] = -0.5f*g_hw[tid]*ksq[tid];
    }
}

// ---------------- v_g mix + mv_transform + Vcat assembly ----------------
__global__ void vg_kernel(const float* __restrict__ gin, const float* __restrict__ W_mg) {
    int n = blockIdx.x, tid = threadIdx.x;   // 128 threads
    __shared__ float cat16[16*16];
    __shared__ float mix[64*16];
    __shared__ float qn[4], tr[3];
    if (tid<4) qn[tid]=g_qn[n*4+tid];
    if (tid>=4 && tid<7) tr[tid-4]=g_tr[n*3+tid-4];
    {
        int p=tid>>4, c=tid&15;
        cat16[p*16+c]     = g_proj[(size_t)n*PROJ_ + 3456 + p*16 + c];
        cat16[(p+8)*16+c] = gin  [(size_t)n*128 + p*16 + c];
    }
    __syncthreads();
    for (int t=tid; t<1024; t+=128) {
        int o=t>>4, c=t&15;
        float acc=0.f;
        #pragma unroll
        for (int i=0;i<16;i++) acc += W_mg[o*16+i]*cat16[i*16+c];
        mix[t]=acc;
    }
    __syncthreads();
    if (tid < 64) {
        int o=tid, h=o>>3, p=o&7;
        float mv[16];
        #pragma unroll
        for (int c=0;c<16;c++) mv[c]=mix[o*16+c];
        float out[16];
        out[0]=mv[0];
        qrot(qn, mv+1, out+1);
        qrot(qn, mv+4, out+4);
        float pv[3]; qrot(qn, mv+7, pv);
        float w=mv[10];
        out[7]=pv[0]+w*tr[0]; out[8]=pv[1]+w*tr[1]; out[9]=pv[2]+w*tr[2];
        #pragma unroll
        for (int c=10;c<16;c++) out[c]=mv[c];
        float* dst = g_Vcat + ((size_t)h*N_+n)*OC_ + 128 + p*16;
        #pragma unroll
        for (int c=0;c<16;c++) dst[c]=out[c];
    }
    for (int t=tid; t<H_*C_; t+=128) {
        int h=t>>7, c=t&127;
        g_Vcat[((size_t)h*N_+n)*OC_ + c] = g_proj[(size_t)n*PROJ_ + 1024 + h*256 + 128 + c];
    }
}

// ---------------- row softmax + fused o_rel accumulation ----------------
__global__ void __launch_bounds__(256) softmax_kernel() {
    __shared__ float qt[512*9];
    int tid = threadIdx.x;
    int warp = tid >> 5, lane = tid & 31;
    for (int t = tid; t < 512; t += 256) {
        #pragma unroll
        for (int c=0;c<8;c++) qt[t*9+c] = g_qntr[t*8+c];
    }
    __syncthreads();
    int row = blockIdx.x*8 + warp;
    float* a = g_A + (size_t)row*N_;
    float v[16];
    #pragma unroll
    for (int t=0;t<16;t++) v[t] = a[lane + 32*t];
    float m = v[0];
    #pragma unroll
    for (int t=1;t<16;t++) m = fmaxf(m, v[t]);
    #pragma unroll
    for (int off=16; off>0; off>>=1) m = fmaxf(m, __shfl_xor_sync(0xffffffff, m, off));
    float s = 0.f;
    #pragma unroll
    for (int t=0;t<16;t++) { v[t] = expf(v[t]-m); s += v[t]; }
    #pragma unroll
    for (int off=16; off>0; off>>=1) s += __shfl_xor_sync(0xffffffff, s, off);
    float inv = 1.f/s;
    float orel[8] = {};
    #pragma unroll
    for (int t=0;t<16;t++) {
        float p = v[t]*inv;
        a[lane + 32*t] = p;
        const float* q = qt + (lane + 32*t)*9;
        #pragma unroll
        for (int c=0;c<8;c++) orel[c] += p*q[c];
    }
    #pragma unroll
    for (int c=0;c<8;c++) {
        #pragma unroll
        for (int off=16; off>0; off>>=1)
            orel[c] += __shfl_xor_sync(0xffffffff, orel[c], off);
    }
    if (lane == 0) {
        #pragma unroll
        for (int c=0;c<8;c++) g_Orel[(size_t)row*8+c] = orel[c];
    }
}

// ---------------- o_pair (R9 staged) ----------------
__global__ void opair_kernel() {
    int i = blockIdx.x;
    int tid = threadIdx.x;  // 256
    __shared__ float Zs[64*33];
    __shared__ float Asm[8*64];
    int hh = tid>>5, cc = tid&31;
    float acc = 0.f;
    for (int jt=0; jt<N_; jt+=64) {
        __syncthreads();
        for (int t=tid; t<2048; t+=256) {
            int jj=t>>5, c=t&31;
            Zs[jj*33+c] = g_zdz[((size_t)i*N_ + jt+jj)*32 + c];
        }
        for (int t=tid; t<512; t+=256) {
            int h=t>>6, jj=t&63;
            Asm[h*64+jj] = g_A[((size_t)h*N_+i)*N_ + jt+jj];
        }
        __syncthreads();
        #pragma unroll
        for (int jj=0; jj<64; jj++) acc += Asm[hh*64+jj]*Zs[jj*33+cc];
    }
    g_feats[(size_t)i*FEAT_ + hh*SEG_ + cc] = acc;
}

// ---------------- finalize ----------------
__global__ void finalize_kernel() {
    int n = blockIdx.x, tid = threadIdx.x;  // 128
    __shared__ float qn[4], tr[3];
    if (tid<4) qn[tid]=g_qn[n*4+tid];
    if (tid>=4 && tid<7) tr[tid-4]=g_tr[n*3+tid-4];
    __syncthreads();
    for (int t=tid; t<H_*C_; t+=128) {
        int h=t>>7, c=t&127;
        g_feats[(size_t)n*FEAT_ + h*SEG_ + 32 + c] = g_Ocat[((size_t)h*N_+n)*OC_ + c];
    }
    if (tid < 64) {
        int h=tid>>3, p=tid&7;
        const float* oc = g_Ocat + ((size_t)h*N_+n)*OC_ + 128 + p*16;
        float mv[16];
        #pragma unroll
        for (int c=0;c<16;c++) mv[c]=oc[c];
        float qc[4] = {qn[0], -qn[1], -qn[2], -qn[3]};
        float out[16];
        out[0]=mv[0];
        qrot(qc, mv+1, out+1);
        qrot(qc, mv+4, out+4);
        float w=mv[10];
        float tmp[3] = {mv[7]-w*tr[0], mv[8]-w*tr[1], mv[9]-w*tr[2]};
        qrot(qc, tmp, out+7);
        #pragma unroll
        for (int c=10;c<16;c++) out[c]=mv[c];
        float s1v=1e-8f, s2v=1e-8f;
        #pragma unroll
        for (int c=0;c<10;c++) s1v += out[c]*out[c];
        #pragma unroll
        for (int c=10;c<16;c++) s2v += out[c]*out[c];
        float* f = g_feats + (size_t)n*FEAT_ + h*SEG_;
        #pragma unroll
        for (int c=0;c<16;c++) f[168+p*16+c]=out[c];
        f[296+p*2+0]=sqrtf(s1v);
        f[296+p*2+1]=sqrtf(s2v);
    }
    if (tid < H_) {
        int h=tid;
        const float* oc = g_Orel + ((size_t)h*N_+n)*8;
        float aq0=oc[0], aq1=oc[1], aq2=oc[2], aq3=oc[3];
        float qc[4] = {qn[0], -qn[1], -qn[2], -qn[3]};
        float qr0 = qc[0]*aq0 - qc[1]*aq1 - qc[2]*aq2 - qc[3]*aq3;
        float qr1 = qc[0]*aq1 + qc[1]*aq0 + qc[2]*aq3 - qc[3]*aq2;
        float qr2 = qc[0]*aq2 - qc[1]*aq3 + qc[2]*aq0 + qc[3]*aq1;
        float qr3 = qc[0]*aq3 + qc[1]*aq2 - qc[2]*aq1 + qc[3]*aq0;
        float d[3] = {oc[4]-tr[0], oc[5]-tr[1], oc[6]-tr[2]};
        float trel[3];
        qrot(qc, d, trel);
        float* f = g_feats + (size_t)n*FEAT_ + h*SEG_ + 160;
        f[0]=qr0; f[1]=qr1; f[2]=qr2; f[3]=qr3;
        f[4]=trel[0]; f[5]=trel[1]; f[6]=trel[2]; f[7]=0.f;
    }
}

// ---------------- out init (bias) ----------------
__global__ void out_init_kernel(float* __restrict__ out, const float* __restrict__ b_out) {
    int idx = blockIdx.x*256 + threadIdx.x;
    if (idx < 512*384) out[idx] = b_out[idx % 384];
}

// ---------------- g_out ----------------
__global__ void gout_kernel(const float* __restrict__ W_geo, float* __restrict__ out) {
    int n = blockIdx.x, tid = threadIdx.x;  // 128
    int o = tid>>4, c = tid&15;
    float acc = 0.f;
    #pragma unroll
    for (int i2=0; i2<64; i2++) {
        acc += W_geo[o*64+i2] * g_feats[(size_t)n*FEAT_ + (i2>>3)*SEG_ + 168 + (i2&7)*16 + c];
    }
    out[(size_t)n*128 + o*16 + c] = acc;
}

// ---------------- launch ----------------
extern "C" void kernel_launch(void* const* d_in, const int* in_sizes, int n_in,
                              void* d_out, int out_size) {
    const float* s    = (const float*)d_in[0];
    const float* gin  = (const float*)d_in[1];
    const float* z    = (const float*)d_in[2];
    const float* T    = (const float*)d_in[3];
    const float* mask = (const float*)d_in[4];
    const float* W_q  = (const float*)d_in[5];
    const float* b_q  = (const float*)d_in[6];
    const float* W_kv = (const float*)d_in[7];
    const float* b_kv = (const float*)d_in[8];
    const float* W_qp = (const float*)d_in[9];
    const float* b_qp = (const float*)d_in[10];
    const float* W_kp = (const float*)d_in[11];
    const float* b_kp = (const float*)d_in[12];
    const float* W_vg = (const float*)d_in[13];
    const float* b_vg = (const float*)d_in[14];
    const float* W_mg = (const float*)d_in[15];
    const float* W_b  = (const float*)d_in[16];
    const float* b_b  = (const float*)d_in[17];
    const float* W_dz = (const float*)d_in[18];
    const float* b_dz = (const float*)d_in[19];
    const float* head_weights    = (const float*)d_in[20];
    const float* softmax_weights = (const float*)d_in[21];
    const float* W_out = (const float*)d_in[22];
    const float* b_out = (const float*)d_in[23];
    const float* W_geo = (const float*)d_in[24];
    float* out = (float*)d_out;

    setup_kernel<<<(N_ + 40*128 + 255)/256, 256>>>(T, head_weights, W_b, W_dz);
    pack_kernel<<<(384*PROJ_+255)/256,256>>>(W_q,W_kv,W_qp,W_kp,W_vg, b_q,b_kv,b_qp,b_kp,b_vg);
    zfuse_mma<<<1024,256>>>(z, b_dz);

    proj_mma<<<dim3(PROJ_/64, 4), 256>>>(s);

    pts_pack_kernel<<<512,128>>>();
    vg_kernel<<<512,128>>>(gin, W_mg);

    logits_mma<<<dim3(8,4,8), 256>>>(b_b, softmax_weights, mask);
    softmax_kernel<<<512,256>>>();
    av_mma<<<dim3(4,4,8), 256>>>();
    opair_kernel<<<512,256>>>();
    finalize_kernel<<<512,128>>>();

    out_init_kernel<<<768,256>>>(out, b_out);
    wout_mma<<<dim3(6,4,6), 256>>>(W_out, out);
    gout_kernel<<<512,128>>>(W_geo, out + 512*384);
}